// round 1
// baseline (speedup 1.0000x reference)
#include <cuda_runtime.h>
#include <cuda_bf16.h>
#include <math.h>

// Problem dims (fixed)
#define BATCH 2
#define SEQ   2048
#define DIM   1024
#define NHEAD 16
#define HDIM  64
#define DIM3  (3*DIM)
#define MROWS (BATCH*SEQ)      // 4096
#define ATT_SCALE 0.125f       // 64^-0.5

// Scratch (device globals; allocation-free rule)
__device__ float g_qkv [ (size_t)BATCH * SEQ * DIM3 ];   // 50 MB
__device__ float g_attn[ (size_t)BATCH * SEQ * DIM  ];   // 16 MB

// ---------------------------------------------------------------------------
// Classic SGEMM: C[M,N] = A[M,K] @ B[K,N], all row-major fp32.
// 128x128 block tile, BK=16, 256 threads, 8x8 per-thread register tile.
// Requires M%128==0, N%128==0, K%16==0 (true for all our shapes).
// ---------------------------------------------------------------------------
__global__ __launch_bounds__(256, 2)
void sgemm128(const float* __restrict__ A, const float* __restrict__ B,
              float* __restrict__ C, int M, int N, int K)
{
    __shared__ float As[16][132];   // [k][m], padded
    __shared__ float Bs[16][128];   // [k][n]

    const int tid = threadIdx.x;
    const int bm  = blockIdx.y * 128;
    const int bn  = blockIdx.x * 128;
    const int ty  = tid >> 4;       // 0..15
    const int tx  = tid & 15;       // 0..15

    float acc[8][8];
#pragma unroll
    for (int i = 0; i < 8; i++)
#pragma unroll
        for (int j = 0; j < 8; j++) acc[i][j] = 0.f;

    for (int k0 = 0; k0 < K; k0 += 16) {
        // Load A tile 128x16 -> As transposed [k][m]
#pragma unroll
        for (int u = 0; u < 2; u++) {
            int f4 = tid * 2 + u;                 // 0..511
            int r  = f4 >> 2;                     // 0..127
            int c4 = (f4 & 3) << 2;               // 0,4,8,12
            float4 v = *(const float4*)&A[(size_t)(bm + r) * K + k0 + c4];
            As[c4 + 0][r] = v.x;
            As[c4 + 1][r] = v.y;
            As[c4 + 2][r] = v.z;
            As[c4 + 3][r] = v.w;
        }
        // Load B tile 16x128 -> Bs [k][n]
#pragma unroll
        for (int u = 0; u < 2; u++) {
            int f4 = tid * 2 + u;
            int r  = f4 >> 5;                     // 0..15
            int c4 = (f4 & 31) << 2;              // 0..124
            *(float4*)&Bs[r][c4] = *(const float4*)&B[(size_t)(k0 + r) * N + bn + c4];
        }
        __syncthreads();

#pragma unroll
        for (int kk = 0; kk < 16; kk++) {
            float a[8], b[8];
            *(float4*)&a[0] = *(const float4*)&As[kk][ty * 8];
            *(float4*)&a[4] = *(const float4*)&As[kk][ty * 8 + 4];
            *(float4*)&b[0] = *(const float4*)&Bs[kk][tx * 8];
            *(float4*)&b[4] = *(const float4*)&Bs[kk][tx * 8 + 4];
#pragma unroll
            for (int i = 0; i < 8; i++)
#pragma unroll
                for (int j = 0; j < 8; j++)
                    acc[i][j] = fmaf(a[i], b[j], acc[i][j]);
        }
        __syncthreads();
    }

#pragma unroll
    for (int i = 0; i < 8; i++) {
        int r = bm + ty * 8 + i;
        float4 v0 = make_float4(acc[i][0], acc[i][1], acc[i][2], acc[i][3]);
        float4 v1 = make_float4(acc[i][4], acc[i][5], acc[i][6], acc[i][7]);
        *(float4*)&C[(size_t)r * N + bn + tx * 8]     = v0;
        *(float4*)&C[(size_t)r * N + bn + tx * 8 + 4] = v1;
    }
}

// ---------------------------------------------------------------------------
// Flash-attention (fp32). One block = 64 queries of one (batch, head).
// 128 threads. K/V tiles of 32 rows. Online softmax, O accumulated in regs.
// qkv layout: [B][S][3*DIM] with col = which*1024 + h*64 + d.
// out layout:  [B][S][DIM]  with col = h*64 + d.
// ---------------------------------------------------------------------------
__global__ __launch_bounds__(128, 4)
void attn_kernel(const float* __restrict__ qkv, float* __restrict__ out)
{
    __shared__ float Qt[64][68];   // [d][r]
    __shared__ float Kt[64][36];   // [d][c]
    __shared__ float Pt[32][68];   // [t][r]
    __shared__ float Vs[32][68];   // [t][d]

    const int tid = threadIdx.x;         // 0..127
    const int ty  = tid >> 3;            // 0..15  (query-row group)
    const int tx  = tid & 7;             // 0..7
    const int s0  = blockIdx.x * 64;
    const int h   = blockIdx.y;
    const int b   = blockIdx.z;

    const float* qbase = qkv + (size_t)b * SEQ * DIM3 + h * HDIM;
    const float* kbase = qbase + DIM;
    const float* vbase = qbase + 2 * DIM;

    // ---- Load Q tile transposed: Qt[d][r] ----
#pragma unroll
    for (int u = 0; u < 8; u++) {
        int idx = tid + u * 128;         // 0..1023
        int r   = idx >> 4;              // 0..63
        int d4  = (idx & 15) << 2;       // 0..60
        float4 v = *(const float4*)&qbase[(size_t)(s0 + r) * DIM3 + d4];
        Qt[d4 + 0][r] = v.x;
        Qt[d4 + 1][r] = v.y;
        Qt[d4 + 2][r] = v.z;
        Qt[d4 + 3][r] = v.w;
    }

    float m_run[4], l_run[4];
    float o[4][8];
#pragma unroll
    for (int i = 0; i < 4; i++) {
        m_run[i] = -1e30f;
        l_run[i] = 0.f;
#pragma unroll
        for (int j = 0; j < 8; j++) o[i][j] = 0.f;
    }

    for (int t0 = 0; t0 < SEQ; t0 += 32) {
        __syncthreads();   // previous iter done using Kt/Vs/Pt
        // ---- Load K (transposed) + V tiles ----
#pragma unroll
        for (int u = 0; u < 4; u++) {
            int idx = tid + u * 128;     // 0..511
            int c   = idx >> 4;          // 0..31
            int d4  = (idx & 15) << 2;
            float4 kv = *(const float4*)&kbase[(size_t)(t0 + c) * DIM3 + d4];
            Kt[d4 + 0][c] = kv.x;
            Kt[d4 + 1][c] = kv.y;
            Kt[d4 + 2][c] = kv.z;
            Kt[d4 + 3][c] = kv.w;
            float4 vv = *(const float4*)&vbase[(size_t)(t0 + c) * DIM3 + d4];
            *(float4*)&Vs[c][d4] = vv;
        }
        __syncthreads();

        // ---- GEMM1: S(64x32) = Q @ K^T ----
        float sreg[4][4];
#pragma unroll
        for (int i = 0; i < 4; i++)
#pragma unroll
            for (int j = 0; j < 4; j++) sreg[i][j] = 0.f;

#pragma unroll
        for (int d = 0; d < 64; d++) {
            float a[4], bb[4];
            *(float4*)a  = *(const float4*)&Qt[d][ty * 4];
            *(float4*)bb = *(const float4*)&Kt[d][tx * 4];
#pragma unroll
            for (int i = 0; i < 4; i++)
#pragma unroll
                for (int j = 0; j < 4; j++)
                    sreg[i][j] = fmaf(a[i], bb[j], sreg[i][j]);
        }

        // ---- Online softmax (row reductions across the 8 tx lanes) ----
#pragma unroll
        for (int i = 0; i < 4; i++) {
            float mx = -1e30f;
#pragma unroll
            for (int j = 0; j < 4; j++) {
                sreg[i][j] *= ATT_SCALE;
                mx = fmaxf(mx, sreg[i][j]);
            }
#pragma unroll
            for (int off = 1; off < 8; off <<= 1)
                mx = fmaxf(mx, __shfl_xor_sync(0xffffffffu, mx, off));

            float m_new = fmaxf(m_run[i], mx);
            float alpha = __expf(m_run[i] - m_new);
            float p[4];
            float rs = 0.f;
#pragma unroll
            for (int j = 0; j < 4; j++) {
                p[j] = __expf(sreg[i][j] - m_new);
                rs += p[j];
            }
#pragma unroll
            for (int off = 1; off < 8; off <<= 1)
                rs += __shfl_xor_sync(0xffffffffu, rs, off);

            l_run[i] = l_run[i] * alpha + rs;
            m_run[i] = m_new;
#pragma unroll
            for (int j = 0; j < 8; j++) o[i][j] *= alpha;
#pragma unroll
            for (int j = 0; j < 4; j++)
                Pt[tx * 4 + j][ty * 4 + i] = p[j];
        }
        __syncthreads();   // Pt visible to everyone

        // ---- GEMM2: O(64x64) += P @ V ----
#pragma unroll
        for (int t = 0; t < 32; t++) {
            float a[4], bb[8];
            *(float4*)a      = *(const float4*)&Pt[t][ty * 4];
            *(float4*)&bb[0] = *(const float4*)&Vs[t][tx * 8];
            *(float4*)&bb[4] = *(const float4*)&Vs[t][tx * 8 + 4];
#pragma unroll
            for (int i = 0; i < 4; i++)
#pragma unroll
                for (int j = 0; j < 8; j++)
                    o[i][j] = fmaf(a[i], bb[j], o[i][j]);
        }
    }

    // ---- Normalize + write ----
    float* obase = out + (size_t)b * SEQ * DIM + h * HDIM;
#pragma unroll
    for (int i = 0; i < 4; i++) {
        float inv = 1.f / l_run[i];
        int r = s0 + ty * 4 + i;
        float4 v0 = make_float4(o[i][0]*inv, o[i][1]*inv, o[i][2]*inv, o[i][3]*inv);
        float4 v1 = make_float4(o[i][4]*inv, o[i][5]*inv, o[i][6]*inv, o[i][7]*inv);
        *(float4*)&obase[(size_t)r * DIM + tx * 8]     = v0;
        *(float4*)&obase[(size_t)r * DIM + tx * 8 + 4] = v1;
    }
}

// ---------------------------------------------------------------------------
extern "C" void kernel_launch(void* const* d_in, const int* in_sizes, int n_in,
                              void* d_out, int out_size)
{
    const float* x     = (const float*)d_in[0];   // [B,S,DIM]
    const float* Wqkv  = (const float*)d_in[1];   // [DIM, 3*DIM]
    const float* Wproj = (const float*)d_in[2];   // [DIM, DIM]
    float*       outp  = (float*)d_out;           // [B,S,DIM]

    float* qkv;  cudaGetSymbolAddress((void**)&qkv,  g_qkv);
    float* attn; cudaGetSymbolAddress((void**)&attn, g_attn);

    // 1) qkv = x @ Wqkv    (M=4096, N=3072, K=1024)
    {
        dim3 grid(DIM3 / 128, MROWS / 128);
        sgemm128<<<grid, 256>>>(x, Wqkv, qkv, MROWS, DIM3, DIM);
    }
    // 2) attention
    {
        dim3 grid(SEQ / 64, NHEAD, BATCH);
        attn_kernel<<<grid, 128>>>(qkv, attn);
    }
    // 3) out = attn @ Wproj (M=4096, N=1024, K=1024)
    {
        dim3 grid(DIM / 128, MROWS / 128);
        sgemm128<<<grid, 256>>>(attn, Wproj, outp, MROWS, DIM, DIM);
    }
}

// round 3
// speedup vs baseline: 1.3611x; 1.3611x over previous
#include <cuda_runtime.h>
#include <cuda_bf16.h>
#include <math.h>
#include <stdint.h>

// Problem dims (fixed)
#define BATCH 2
#define SEQ   2048
#define DIM   1024
#define NHEAD 16
#define HDIM  64
#define DIM3  (3*DIM)
#define MROWS (BATCH*SEQ)      // 4096
#define ATT_SCALE 0.125f       // 64^-0.5

// Scratch (device globals; allocation-free rule)
__device__ float g_qkv   [ (size_t)BATCH * SEQ * DIM3 ];   // ~50 MB
__device__ float g_attn  [ (size_t)BATCH * SEQ * DIM  ];   // ~16 MB
__device__ float g_xr    [ (size_t)MROWS * DIM ];          // ~16 MB  (tf32-rounded x)
__device__ float g_wqkvT [ (size_t)DIM3 * DIM ];           // ~12.6 MB (Wqkv^T, tf32-rounded)
__device__ float g_wprojT[ (size_t)DIM  * DIM ];           // ~4.2 MB  (Wproj^T, tf32-rounded)

// ===========================================================================
// helpers
// ===========================================================================
__device__ __forceinline__ uint32_t smem_u32(const void* p) {
    uint32_t a;
    asm("{ .reg .u64 t; cvta.to.shared.u64 t, %1; cvt.u32.u64 %0, t; }" : "=r"(a) : "l"(p));
    return a;
}
__device__ __forceinline__ float to_tf32(float v) {
    float r;
    asm("cvt.rna.tf32.f32 %0, %1;" : "=f"(r) : "f"(v));
    return r;
}
__device__ __forceinline__ void cp_async16(uint32_t saddr, const void* gptr) {
    asm volatile("cp.async.cg.shared.global [%0], [%1], 16;" :: "r"(saddr), "l"(gptr) : "memory");
}
#define CP_COMMIT() asm volatile("cp.async.commit_group;" ::: "memory")
#define CP_WAIT0()  asm volatile("cp.async.wait_group 0;" ::: "memory")

// mma.sync m16n8k8 tf32: D(4xf32) += A(4xtf32) * B(2xtf32)
__device__ __forceinline__ void mma_tf32(float* c, const float* a, const float* b) {
    asm volatile(
        "mma.sync.aligned.m16n8k8.row.col.f32.tf32.tf32.f32 "
        "{%0,%1,%2,%3}, {%4,%5,%6,%7}, {%8,%9}, {%0,%1,%2,%3};"
        : "+f"(c[0]), "+f"(c[1]), "+f"(c[2]), "+f"(c[3])
        : "r"(__float_as_uint(a[0])), "r"(__float_as_uint(a[1])),
          "r"(__float_as_uint(a[2])), "r"(__float_as_uint(a[3])),
          "r"(__float_as_uint(b[0])), "r"(__float_as_uint(b[1])));
}

// ===========================================================================
// prep kernels
// ===========================================================================
__global__ void round_tf32_k(const float* __restrict__ in, float* __restrict__ out, int n4)
{
    int i = blockIdx.x * blockDim.x + threadIdx.x;
    if (i < n4) {
        float4 v = ((const float4*)in)[i];
        v.x = to_tf32(v.x); v.y = to_tf32(v.y); v.z = to_tf32(v.z); v.w = to_tf32(v.w);
        ((float4*)out)[i] = v;
    }
}

// out[C][R] = tf32(in[R][C])
__global__ void transpose_k(const float* __restrict__ in, float* __restrict__ out, int R, int C)
{
    __shared__ float t[32][33];
    int bx = blockIdx.x * 32, by = blockIdx.y * 32;
    int x = bx + threadIdx.x;
#pragma unroll
    for (int j = 0; j < 32; j += 8) {
        int y = by + threadIdx.y + j;
        t[threadIdx.y + j][threadIdx.x] = to_tf32(in[(size_t)y * C + x]);
    }
    __syncthreads();
    int x2 = by + threadIdx.x;
#pragma unroll
    for (int j = 0; j < 32; j += 8) {
        int y2 = bx + threadIdx.y + j;
        out[(size_t)y2 * R + x2] = t[threadIdx.x][threadIdx.y + j];
    }
}

// ===========================================================================
// tf32 mma.sync GEMM: C[M,N] = A[M,K] @ Bt[N,K]^T (both row-major, tf32-rounded)
// 128x128 CTA tile, BK=16, 256 threads (8 warps, 2x4), 64x32 warp tile.
// Double-buffered cp.async. Smem stride 20 floats -> conflict-free frag loads.
// ===========================================================================
#define SA 20
__global__ __launch_bounds__(256)
void gemm_mma(const float* __restrict__ A, const float* __restrict__ Bt,
              float* __restrict__ C, int M, int N, int K)
{
    __shared__ float As[2][128][SA];
    __shared__ float Bs[2][128][SA];

    const int tid  = threadIdx.x;
    const int wid  = tid >> 5;
    const int lane = tid & 31;
    const int g4   = lane >> 2;      // 0..7
    const int l4   = lane & 3;       // 0..3
    const int wm   = (wid >> 2) * 64;
    const int wn   = (wid & 3) * 32;
    const int bm   = blockIdx.y * 128;
    const int bn   = blockIdx.x * 128;

    float acc[4][4][4];
#pragma unroll
    for (int mi = 0; mi < 4; mi++)
#pragma unroll
        for (int ni = 0; ni < 4; ni++)
#pragma unroll
            for (int r = 0; r < 4; r++) acc[mi][ni][r] = 0.f;

    const int KC = K >> 4;   // BK=16 chunks

    auto load_stage = [&](int s, int k0) {
#pragma unroll
        for (int u = 0; u < 2; u++) {
            int ch  = tid * 2 + u;          // 0..511
            int row = ch >> 2;              // 0..127
            int c4  = (ch & 3) << 2;        // 0,4,8,12
            cp_async16(smem_u32(&As[s][row][c4]), A  + (size_t)(bm + row) * K + k0 + c4);
            cp_async16(smem_u32(&Bs[s][row][c4]), Bt + (size_t)(bn + row) * K + k0 + c4);
        }
        CP_COMMIT();
    };

    load_stage(0, 0);
    CP_WAIT0();
    __syncthreads();

    for (int i = 0; i < KC; i++) {
        const int s = i & 1;
        if (i + 1 < KC) load_stage(s ^ 1, (i + 1) << 4);

#pragma unroll
        for (int ks = 0; ks < 2; ks++) {
            const int kc = ks * 8 + l4;
            float a[4][4];
#pragma unroll
            for (int mi = 0; mi < 4; mi++) {
                int m0 = wm + mi * 16 + g4;
                a[mi][0] = As[s][m0    ][kc];
                a[mi][1] = As[s][m0 + 8][kc];
                a[mi][2] = As[s][m0    ][kc + 4];
                a[mi][3] = As[s][m0 + 8][kc + 4];
            }
            float b[4][2];
#pragma unroll
            for (int ni = 0; ni < 4; ni++) {
                int n0 = wn + ni * 8 + g4;
                b[ni][0] = Bs[s][n0][kc];
                b[ni][1] = Bs[s][n0][kc + 4];
            }
#pragma unroll
            for (int mi = 0; mi < 4; mi++)
#pragma unroll
                for (int ni = 0; ni < 4; ni++)
                    mma_tf32(acc[mi][ni], a[mi], b[ni]);
        }

        if (i + 1 < KC) CP_WAIT0();
        __syncthreads();
    }

    // epilogue
#pragma unroll
    for (int mi = 0; mi < 4; mi++) {
        int r0 = bm + wm + mi * 16 + g4;
#pragma unroll
        for (int ni = 0; ni < 4; ni++) {
            int c0 = bn + wn + ni * 8 + 2 * l4;
            float2 v0 = make_float2(acc[mi][ni][0], acc[mi][ni][1]);
            float2 v1 = make_float2(acc[mi][ni][2], acc[mi][ni][3]);
            *(float2*)&C[(size_t)r0 * N + c0]       = v0;
            *(float2*)&C[(size_t)(r0 + 8) * N + c0] = v1;
        }
    }
}

// ===========================================================================
// Flash-attention (fp32) — as round 1, but output rounded to tf32 for GEMM2
// ===========================================================================
__global__ __launch_bounds__(128, 4)
void attn_kernel(const float* __restrict__ qkv, float* __restrict__ out)
{
    __shared__ float Qt[64][68];   // [d][r]
    __shared__ float Kt[64][36];   // [d][c]
    __shared__ float Pt[32][68];   // [t][r]
    __shared__ float Vs[32][68];   // [t][d]

    const int tid = threadIdx.x;
    const int ty  = tid >> 3;
    const int tx  = tid & 7;
    const int s0  = blockIdx.x * 64;
    const int h   = blockIdx.y;
    const int b   = blockIdx.z;

    const float* qbase = qkv + (size_t)b * SEQ * DIM3 + h * HDIM;
    const float* kbase = qbase + DIM;
    const float* vbase = qbase + 2 * DIM;

#pragma unroll
    for (int u = 0; u < 8; u++) {
        int idx = tid + u * 128;
        int r   = idx >> 4;
        int d4  = (idx & 15) << 2;
        float4 v = *(const float4*)&qbase[(size_t)(s0 + r) * DIM3 + d4];
        Qt[d4 + 0][r] = v.x;
        Qt[d4 + 1][r] = v.y;
        Qt[d4 + 2][r] = v.z;
        Qt[d4 + 3][r] = v.w;
    }

    float m_run[4], l_run[4];
    float o[4][8];
#pragma unroll
    for (int i = 0; i < 4; i++) {
        m_run[i] = -1e30f;
        l_run[i] = 0.f;
#pragma unroll
        for (int j = 0; j < 8; j++) o[i][j] = 0.f;
    }

    for (int t0 = 0; t0 < SEQ; t0 += 32) {
        __syncthreads();
#pragma unroll
        for (int u = 0; u < 4; u++) {
            int idx = tid + u * 128;
            int c   = idx >> 4;
            int d4  = (idx & 15) << 2;
            float4 kv = *(const float4*)&kbase[(size_t)(t0 + c) * DIM3 + d4];
            Kt[d4 + 0][c] = kv.x;
            Kt[d4 + 1][c] = kv.y;
            Kt[d4 + 2][c] = kv.z;
            Kt[d4 + 3][c] = kv.w;
            float4 vv = *(const float4*)&vbase[(size_t)(t0 + c) * DIM3 + d4];
            *(float4*)&Vs[c][d4] = vv;
        }
        __syncthreads();

        float sreg[4][4];
#pragma unroll
        for (int i = 0; i < 4; i++)
#pragma unroll
            for (int j = 0; j < 4; j++) sreg[i][j] = 0.f;

#pragma unroll
        for (int d = 0; d < 64; d++) {
            float a[4], bb[4];
            *(float4*)a  = *(const float4*)&Qt[d][ty * 4];
            *(float4*)bb = *(const float4*)&Kt[d][tx * 4];
#pragma unroll
            for (int i = 0; i < 4; i++)
#pragma unroll
                for (int j = 0; j < 4; j++)
                    sreg[i][j] = fmaf(a[i], bb[j], sreg[i][j]);
        }

#pragma unroll
        for (int i = 0; i < 4; i++) {
            float mx = -1e30f;
#pragma unroll
            for (int j = 0; j < 4; j++) {
                sreg[i][j] *= ATT_SCALE;
                mx = fmaxf(mx, sreg[i][j]);
            }
#pragma unroll
            for (int off = 1; off < 8; off <<= 1)
                mx = fmaxf(mx, __shfl_xor_sync(0xffffffffu, mx, off));

            float m_new = fmaxf(m_run[i], mx);
            float alpha = __expf(m_run[i] - m_new);
            float p[4];
            float rs = 0.f;
#pragma unroll
            for (int j = 0; j < 4; j++) {
                p[j] = __expf(sreg[i][j] - m_new);
                rs += p[j];
            }
#pragma unroll
            for (int off = 1; off < 8; off <<= 1)
                rs += __shfl_xor_sync(0xffffffffu, rs, off);

            l_run[i] = l_run[i] * alpha + rs;
            m_run[i] = m_new;
#pragma unroll
            for (int j = 0; j < 8; j++) o[i][j] *= alpha;
#pragma unroll
            for (int j = 0; j < 4; j++)
                Pt[tx * 4 + j][ty * 4 + i] = p[j];
        }
        __syncthreads();

#pragma unroll
        for (int t = 0; t < 32; t++) {
            float a[4], bb[8];
            *(float4*)a      = *(const float4*)&Pt[t][ty * 4];
            *(float4*)&bb[0] = *(const float4*)&Vs[t][tx * 8];
            *(float4*)&bb[4] = *(const float4*)&Vs[t][tx * 8 + 4];
#pragma unroll
            for (int i = 0; i < 4; i++)
#pragma unroll
                for (int j = 0; j < 8; j++)
                    o[i][j] = fmaf(a[i], bb[j], o[i][j]);
        }
    }

    float* obase = out + (size_t)b * SEQ * DIM + h * HDIM;
#pragma unroll
    for (int i = 0; i < 4; i++) {
        float inv = 1.f / l_run[i];
        int r = s0 + ty * 4 + i;
        float4 v0 = make_float4(to_tf32(o[i][0]*inv), to_tf32(o[i][1]*inv),
                                to_tf32(o[i][2]*inv), to_tf32(o[i][3]*inv));
        float4 v1 = make_float4(to_tf32(o[i][4]*inv), to_tf32(o[i][5]*inv),
                                to_tf32(o[i][6]*inv), to_tf32(o[i][7]*inv));
        *(float4*)&obase[(size_t)r * DIM + tx * 8]     = v0;
        *(float4*)&obase[(size_t)r * DIM + tx * 8 + 4] = v1;
    }
}

// ===========================================================================
extern "C" void kernel_launch(void* const* d_in, const int* in_sizes, int n_in,
                              void* d_out, int out_size)
{
    const float* x     = (const float*)d_in[0];   // [B,S,DIM]
    const float* Wqkv  = (const float*)d_in[1];   // [DIM, 3*DIM]
    const float* Wproj = (const float*)d_in[2];   // [DIM, DIM]
    float*       outp  = (float*)d_out;           // [B,S,DIM]

    float* qkv;    cudaGetSymbolAddress((void**)&qkv,    g_qkv);
    float* attn;   cudaGetSymbolAddress((void**)&attn,   g_attn);
    float* xr;     cudaGetSymbolAddress((void**)&xr,     g_xr);
    float* wqkvT;  cudaGetSymbolAddress((void**)&wqkvT,  g_wqkvT);
    float* wprojT; cudaGetSymbolAddress((void**)&wprojT, g_wprojT);

    // 0) operand prep: round x to tf32; transpose+round weights
    {
        int n4 = MROWS * DIM / 4;
        round_tf32_k<<<(n4 + 255) / 256, 256>>>(x, xr, n4);
        transpose_k<<<dim3(DIM3 / 32, DIM / 32), dim3(32, 8)>>>(Wqkv,  wqkvT,  DIM, DIM3);
        transpose_k<<<dim3(DIM  / 32, DIM / 32), dim3(32, 8)>>>(Wproj, wprojT, DIM, DIM);
    }

    // 1) qkv = x @ Wqkv    (M=4096, N=3072, K=1024)
    gemm_mma<<<dim3(DIM3 / 128, MROWS / 128), 256>>>(xr, wqkvT, qkv, MROWS, DIM3, DIM);

    // 2) attention
    attn_kernel<<<dim3(SEQ / 64, NHEAD, BATCH), 128>>>(qkv, attn);

    // 3) out = attn @ Wproj (M=4096, N=1024, K=1024)
    gemm_mma<<<dim3(DIM / 128, MROWS / 128), 256>>>(attn, wprojT, outp, MROWS, DIM, DIM);
}

// round 4
// speedup vs baseline: 2.7186x; 1.9974x over previous
#include <cuda_runtime.h>
#include <cuda_bf16.h>
#include <math.h>
#include <stdint.h>

// Problem dims (fixed)
#define BATCH 2
#define SEQ   2048
#define DIM   1024
#define NHEAD 16
#define HDIM  64
#define DIM3  (3*DIM)
#define MROWS (BATCH*SEQ)      // 4096
#define ATT_SCALE 0.125f       // 64^-0.5
#define SCALE_LOG2E 0.1803368801111729f   // ATT_SCALE * log2(e)

// Scratch (device globals; allocation-free rule)
__device__ float g_qkv   [ (size_t)BATCH * SEQ * DIM3 ];   // ~50 MB (tf32-rounded)
__device__ float g_attn  [ (size_t)BATCH * SEQ * DIM  ];   // ~16 MB (tf32-rounded)
__device__ float g_xr    [ (size_t)MROWS * DIM ];          // ~16 MB  (tf32-rounded x)
__device__ float g_wqkvT [ (size_t)DIM3 * DIM ];           // (Wqkv^T, tf32-rounded)
__device__ float g_wprojT[ (size_t)DIM  * DIM ];           // (Wproj^T, tf32-rounded)

// ===========================================================================
// helpers
// ===========================================================================
__device__ __forceinline__ uint32_t smem_u32(const void* p) {
    uint32_t a;
    asm("{ .reg .u64 t; cvta.to.shared.u64 t, %1; cvt.u32.u64 %0, t; }" : "=r"(a) : "l"(p));
    return a;
}
__device__ __forceinline__ float to_tf32(float v) {
    float r;
    asm("cvt.rna.tf32.f32 %0, %1;" : "=f"(r) : "f"(v));
    return r;
}
__device__ __forceinline__ float fast_exp2(float x) {
    float y;
    asm("ex2.approx.ftz.f32 %0, %1;" : "=f"(y) : "f"(x));
    return y;
}
__device__ __forceinline__ void cp_async16(uint32_t saddr, const void* gptr) {
    asm volatile("cp.async.cg.shared.global [%0], [%1], 16;" :: "r"(saddr), "l"(gptr) : "memory");
}
#define CP_COMMIT() asm volatile("cp.async.commit_group;" ::: "memory")
#define CP_WAIT0()  asm volatile("cp.async.wait_group 0;" ::: "memory")
#define CP_WAIT1()  asm volatile("cp.async.wait_group 1;" ::: "memory")

// mma.sync m16n8k8 tf32: D(4xf32) += A(4xtf32) * B(2xtf32)
__device__ __forceinline__ void mma_tf32(float* c, const float* a, const float* b) {
    asm volatile(
        "mma.sync.aligned.m16n8k8.row.col.f32.tf32.tf32.f32 "
        "{%0,%1,%2,%3}, {%4,%5,%6,%7}, {%8,%9}, {%0,%1,%2,%3};"
        : "+f"(c[0]), "+f"(c[1]), "+f"(c[2]), "+f"(c[3])
        : "r"(__float_as_uint(a[0])), "r"(__float_as_uint(a[1])),
          "r"(__float_as_uint(a[2])), "r"(__float_as_uint(a[3])),
          "r"(__float_as_uint(b[0])), "r"(__float_as_uint(b[1])));
}

// ===========================================================================
// prep kernels
// ===========================================================================
__global__ void round_tf32_k(const float* __restrict__ in, float* __restrict__ out, int n4)
{
    int i = blockIdx.x * blockDim.x + threadIdx.x;
    if (i < n4) {
        float4 v = ((const float4*)in)[i];
        v.x = to_tf32(v.x); v.y = to_tf32(v.y); v.z = to_tf32(v.z); v.w = to_tf32(v.w);
        ((float4*)out)[i] = v;
    }
}

// out[C][R] = tf32(in[R][C])
__global__ void transpose_k(const float* __restrict__ in, float* __restrict__ out, int R, int C)
{
    __shared__ float t[32][33];
    int bx = blockIdx.x * 32, by = blockIdx.y * 32;
    int x = bx + threadIdx.x;
#pragma unroll
    for (int j = 0; j < 32; j += 8) {
        int y = by + threadIdx.y + j;
        t[threadIdx.y + j][threadIdx.x] = to_tf32(in[(size_t)y * C + x]);
    }
    __syncthreads();
    int x2 = by + threadIdx.x;
#pragma unroll
    for (int j = 0; j < 32; j += 8) {
        int y2 = bx + threadIdx.y + j;
        out[(size_t)y2 * R + x2] = t[threadIdx.x][threadIdx.y + j];
    }
}

// ===========================================================================
// tf32 mma.sync GEMM: C[M,N] = A[M,K] @ Bt[N,K]^T (both row-major, tf32-rounded)
// ROUND_OUT: round C to tf32 at store (for buffers later consumed as mma operands)
// ===========================================================================
#define SA 20
template<bool ROUND_OUT>
__global__ __launch_bounds__(256)
void gemm_mma(const float* __restrict__ A, const float* __restrict__ Bt,
              float* __restrict__ C, int M, int N, int K)
{
    __shared__ float As[2][128][SA];
    __shared__ float Bs[2][128][SA];

    const int tid  = threadIdx.x;
    const int wid  = tid >> 5;
    const int lane = tid & 31;
    const int g4   = lane >> 2;
    const int l4   = lane & 3;
    const int wm   = (wid >> 2) * 64;
    const int wn   = (wid & 3) * 32;
    const int bm   = blockIdx.y * 128;
    const int bn   = blockIdx.x * 128;

    float acc[4][4][4];
#pragma unroll
    for (int mi = 0; mi < 4; mi++)
#pragma unroll
        for (int ni = 0; ni < 4; ni++)
#pragma unroll
            for (int r = 0; r < 4; r++) acc[mi][ni][r] = 0.f;

    const int KC = K >> 4;

    auto load_stage = [&](int s, int k0) {
#pragma unroll
        for (int u = 0; u < 2; u++) {
            int ch  = tid * 2 + u;
            int row = ch >> 2;
            int c4  = (ch & 3) << 2;
            cp_async16(smem_u32(&As[s][row][c4]), A  + (size_t)(bm + row) * K + k0 + c4);
            cp_async16(smem_u32(&Bs[s][row][c4]), Bt + (size_t)(bn + row) * K + k0 + c4);
        }
        CP_COMMIT();
    };

    load_stage(0, 0);
    CP_WAIT0();
    __syncthreads();

    for (int i = 0; i < KC; i++) {
        const int s = i & 1;
        if (i + 1 < KC) load_stage(s ^ 1, (i + 1) << 4);

#pragma unroll
        for (int ks = 0; ks < 2; ks++) {
            const int kc = ks * 8 + l4;
            float a[4][4];
#pragma unroll
            for (int mi = 0; mi < 4; mi++) {
                int m0 = wm + mi * 16 + g4;
                a[mi][0] = As[s][m0    ][kc];
                a[mi][1] = As[s][m0 + 8][kc];
                a[mi][2] = As[s][m0    ][kc + 4];
                a[mi][3] = As[s][m0 + 8][kc + 4];
            }
            float b[4][2];
#pragma unroll
            for (int ni = 0; ni < 4; ni++) {
                int n0 = wn + ni * 8 + g4;
                b[ni][0] = Bs[s][n0][kc];
                b[ni][1] = Bs[s][n0][kc + 4];
            }
#pragma unroll
            for (int mi = 0; mi < 4; mi++)
#pragma unroll
                for (int ni = 0; ni < 4; ni++)
                    mma_tf32(acc[mi][ni], a[mi], b[ni]);
        }

        if (i + 1 < KC) CP_WAIT0();
        __syncthreads();
    }

#pragma unroll
    for (int mi = 0; mi < 4; mi++) {
        int r0 = bm + wm + mi * 16 + g4;
#pragma unroll
        for (int ni = 0; ni < 4; ni++) {
            int c0 = bn + wn + ni * 8 + 2 * l4;
            float v0 = acc[mi][ni][0], v1 = acc[mi][ni][1];
            float v2 = acc[mi][ni][2], v3 = acc[mi][ni][3];
            if (ROUND_OUT) { v0 = to_tf32(v0); v1 = to_tf32(v1); v2 = to_tf32(v2); v3 = to_tf32(v3); }
            *(float2*)&C[(size_t)r0 * N + c0]       = make_float2(v0, v1);
            *(float2*)&C[(size_t)(r0 + 8) * N + c0] = make_float2(v2, v3);
        }
    }
}

// ===========================================================================
// Tensor-core flash attention (tf32 mma.sync).
// Block = 128 queries x one (b,h). 256 threads, 8 warps; warp owns 16 rows.
// K/V tiles of 64, cp.async double-buffered. Online softmax in base-2.
// qkv is pre-rounded to tf32 (GEMM1 epilogue). P rounded at smem store.
// ===========================================================================
struct AttnSmem {
    float Qs[128][68];      // [q][d]
    float Ks[2][64][68];    // [t][d]
    float Vs[2][64][68];    // [t][d]
    float Ps[128][68];      // [q][t]
};
#define ATTN_SMEM_BYTES ((int)sizeof(AttnSmem))

__global__ __launch_bounds__(256)
void attn_mma(const float* __restrict__ qkv, float* __restrict__ out)
{
    extern __shared__ char sm_raw[];
    AttnSmem& S = *reinterpret_cast<AttnSmem*>(sm_raw);

    const int tid  = threadIdx.x;
    const int wid  = tid >> 5;
    const int lane = tid & 31;
    const int g4   = lane >> 2;
    const int l4   = lane & 3;
    const int q0   = blockIdx.x * 128;
    const int h    = blockIdx.y;
    const int b    = blockIdx.z;
    const int qrow = wid * 16;

    const float* base = qkv + (size_t)b * SEQ * DIM3 + h * HDIM;
    const float* qg = base;
    const float* kg = base + DIM;
    const float* vg = base + 2 * DIM;

    // ---- load Q tile (128x64) via cp.async ----
#pragma unroll
    for (int u = 0; u < 8; u++) {
        int ch = tid + u * 256;          // 0..2047
        int r  = ch >> 4;
        int c4 = (ch & 15) << 2;
        cp_async16(smem_u32(&S.Qs[r][c4]), qg + (size_t)(q0 + r) * DIM3 + c4);
    }
    CP_COMMIT();

    auto load_kv = [&](int s, int t0) {
#pragma unroll
        for (int u = 0; u < 4; u++) {
            int ch = tid + u * 256;      // 0..1023
            int r  = ch >> 4;
            int c4 = (ch & 15) << 2;
            cp_async16(smem_u32(&S.Ks[s][r][c4]), kg + (size_t)(t0 + r) * DIM3 + c4);
            cp_async16(smem_u32(&S.Vs[s][r][c4]), vg + (size_t)(t0 + r) * DIM3 + c4);
        }
        CP_COMMIT();
    };

    load_kv(0, 0);
    CP_WAIT0();
    __syncthreads();

    float m2[2] = { -1e30f, -1e30f };
    float l[2]  = { 0.f, 0.f };
    float O[8][4];
#pragma unroll
    for (int ni = 0; ni < 8; ni++)
#pragma unroll
        for (int r = 0; r < 4; r++) O[ni][r] = 0.f;

    const int NT = SEQ / 64;   // 32 key tiles

    for (int it = 0; it < NT; it++) {
        const int s = it & 1;
        if (it + 1 < NT) {
            load_kv(s ^ 1, (it + 1) * 64);
            CP_WAIT1();
        } else {
            CP_WAIT0();
        }
        __syncthreads();

        // ---- QK^T: sreg[128-row strip: this warp's 16 rows x 64 cols] ----
        float sreg[8][4];
#pragma unroll
        for (int ni = 0; ni < 8; ni++)
#pragma unroll
            for (int r = 0; r < 4; r++) sreg[ni][r] = 0.f;

#pragma unroll
        for (int kt = 0; kt < 8; kt++) {
            const int kc = kt * 8 + l4;
            float a[4];
            a[0] = S.Qs[qrow + g4    ][kc];
            a[1] = S.Qs[qrow + g4 + 8][kc];
            a[2] = S.Qs[qrow + g4    ][kc + 4];
            a[3] = S.Qs[qrow + g4 + 8][kc + 4];
#pragma unroll
            for (int ni = 0; ni < 8; ni++) {
                float bb[2];
                bb[0] = S.Ks[s][ni * 8 + g4][kc];
                bb[1] = S.Ks[s][ni * 8 + g4][kc + 4];
                mma_tf32(sreg[ni], a, bb);
            }
        }

        // ---- online softmax (base-2 domain) ----
        float mx0 = -1e30f, mx1 = -1e30f;
#pragma unroll
        for (int ni = 0; ni < 8; ni++) {
            sreg[ni][0] *= SCALE_LOG2E; sreg[ni][1] *= SCALE_LOG2E;
            sreg[ni][2] *= SCALE_LOG2E; sreg[ni][3] *= SCALE_LOG2E;
            mx0 = fmaxf(mx0, fmaxf(sreg[ni][0], sreg[ni][1]));
            mx1 = fmaxf(mx1, fmaxf(sreg[ni][2], sreg[ni][3]));
        }
        mx0 = fmaxf(mx0, __shfl_xor_sync(0xffffffffu, mx0, 1));
        mx0 = fmaxf(mx0, __shfl_xor_sync(0xffffffffu, mx0, 2));
        mx1 = fmaxf(mx1, __shfl_xor_sync(0xffffffffu, mx1, 1));
        mx1 = fmaxf(mx1, __shfl_xor_sync(0xffffffffu, mx1, 2));

        const float mn0 = fmaxf(m2[0], mx0);
        const float mn1 = fmaxf(m2[1], mx1);
        const float al0 = fast_exp2(m2[0] - mn0);
        const float al1 = fast_exp2(m2[1] - mn1);

        float s0 = 0.f, s1 = 0.f;
#pragma unroll
        for (int ni = 0; ni < 8; ni++) {
            float p0 = fast_exp2(sreg[ni][0] - mn0);
            float p1 = fast_exp2(sreg[ni][1] - mn0);
            float p2 = fast_exp2(sreg[ni][2] - mn1);
            float p3 = fast_exp2(sreg[ni][3] - mn1);
            s0 += p0 + p1;
            s1 += p2 + p3;
            const int col = ni * 8 + 2 * l4;
            *(float2*)&S.Ps[qrow + g4    ][col] = make_float2(to_tf32(p0), to_tf32(p1));
            *(float2*)&S.Ps[qrow + g4 + 8][col] = make_float2(to_tf32(p2), to_tf32(p3));
        }
        s0 += __shfl_xor_sync(0xffffffffu, s0, 1);
        s0 += __shfl_xor_sync(0xffffffffu, s0, 2);
        s1 += __shfl_xor_sync(0xffffffffu, s1, 1);
        s1 += __shfl_xor_sync(0xffffffffu, s1, 2);

        l[0] = l[0] * al0 + s0;
        l[1] = l[1] * al1 + s1;
        m2[0] = mn0;
        m2[1] = mn1;

#pragma unroll
        for (int ni = 0; ni < 8; ni++) {
            O[ni][0] *= al0; O[ni][1] *= al0;
            O[ni][2] *= al1; O[ni][3] *= al1;
        }
        __syncwarp();

        // ---- P @ V: accumulate into O ----
#pragma unroll
        for (int kt = 0; kt < 8; kt++) {
            const int kc = kt * 8 + l4;     // t index within tile
            float a[4];
            a[0] = S.Ps[qrow + g4    ][kc];
            a[1] = S.Ps[qrow + g4 + 8][kc];
            a[2] = S.Ps[qrow + g4    ][kc + 4];
            a[3] = S.Ps[qrow + g4 + 8][kc + 4];
#pragma unroll
            for (int ni = 0; ni < 8; ni++) {
                float bb[2];
                bb[0] = S.Vs[s][kc    ][ni * 8 + g4];
                bb[1] = S.Vs[s][kc + 4][ni * 8 + g4];
                mma_tf32(O[ni], a, bb);
            }
        }
        __syncthreads();
    }

    // ---- normalize + store (rounded tf32 for GEMM2's A operand) ----
    const float inv0 = 1.f / l[0];
    const float inv1 = 1.f / l[1];
    float* ob = out + (size_t)b * SEQ * DIM + h * HDIM;
    const int r0 = q0 + qrow + g4;
#pragma unroll
    for (int ni = 0; ni < 8; ni++) {
        const int col = ni * 8 + 2 * l4;
        *(float2*)&ob[(size_t)r0 * DIM + col] =
            make_float2(to_tf32(O[ni][0] * inv0), to_tf32(O[ni][1] * inv0));
        *(float2*)&ob[(size_t)(r0 + 8) * DIM + col] =
            make_float2(to_tf32(O[ni][2] * inv1), to_tf32(O[ni][3] * inv1));
    }
}

// ===========================================================================
extern "C" void kernel_launch(void* const* d_in, const int* in_sizes, int n_in,
                              void* d_out, int out_size)
{
    const float* x     = (const float*)d_in[0];   // [B,S,DIM]
    const float* Wqkv  = (const float*)d_in[1];   // [DIM, 3*DIM]
    const float* Wproj = (const float*)d_in[2];   // [DIM, DIM]
    float*       outp  = (float*)d_out;           // [B,S,DIM]

    float* qkv;    cudaGetSymbolAddress((void**)&qkv,    g_qkv);
    float* attn;   cudaGetSymbolAddress((void**)&attn,   g_attn);
    float* xr;     cudaGetSymbolAddress((void**)&xr,     g_xr);
    float* wqkvT;  cudaGetSymbolAddress((void**)&wqkvT,  g_wqkvT);
    float* wprojT; cudaGetSymbolAddress((void**)&wprojT, g_wprojT);

    static bool attr_set = false;
    if (!attr_set) {
        cudaFuncSetAttribute(attn_mma, cudaFuncAttributeMaxDynamicSharedMemorySize,
                             ATTN_SMEM_BYTES);
        attr_set = true;
    }

    // 0) operand prep
    {
        int n4 = MROWS * DIM / 4;
        round_tf32_k<<<(n4 + 255) / 256, 256>>>(x, xr, n4);
        transpose_k<<<dim3(DIM3 / 32, DIM / 32), dim3(32, 8)>>>(Wqkv,  wqkvT,  DIM, DIM3);
        transpose_k<<<dim3(DIM  / 32, DIM / 32), dim3(32, 8)>>>(Wproj, wprojT, DIM, DIM);
    }

    // 1) qkv = x @ Wqkv  (rounded to tf32 for attention mma operands)
    gemm_mma<true><<<dim3(DIM3 / 128, MROWS / 128), 256>>>(xr, wqkvT, qkv, MROWS, DIM3, DIM);

    // 2) attention (tensor core)
    attn_mma<<<dim3(SEQ / 128, NHEAD, BATCH), 256, ATTN_SMEM_BYTES>>>(qkv, attn);

    // 3) out = attn @ Wproj (full fp32 output)
    gemm_mma<false><<<dim3(DIM / 128, MROWS / 128), 256>>>(attn, wprojT, outp, MROWS, DIM, DIM);
}

// round 5
// speedup vs baseline: 6.1541x; 2.2637x over previous
#include <cuda_runtime.h>
#include <cuda_fp16.h>
#include <math.h>
#include <stdint.h>

// Problem dims (fixed)
#define BATCH 2
#define SEQ   2048
#define DIM   1024
#define NHEAD 16
#define HDIM  64
#define DIM3  (3*DIM)
#define MROWS (BATCH*SEQ)      // 4096
#define SCALE_LOG2E 0.1803368801111729f   // 64^-0.5 * log2(e)

// Scratch (device globals; allocation-free rule)
__device__ __half g_qkvh  [ (size_t)BATCH * SEQ * DIM3 ];  // 25 MB
__device__ __half g_attnh [ (size_t)BATCH * SEQ * DIM  ];  // 8.4 MB
__device__ __half g_xh    [ (size_t)MROWS * DIM ];         // 8.4 MB
__device__ __half g_wqkvTh[ (size_t)DIM3 * DIM ];          // 6.3 MB  (Wqkv^T)
__device__ __half g_wprojTh[ (size_t)DIM * DIM ];          // 2.1 MB  (Wproj^T)

// ===========================================================================
// helpers
// ===========================================================================
__device__ __forceinline__ uint32_t smem_u32(const void* p) {
    uint32_t a;
    asm("{ .reg .u64 t; cvta.to.shared.u64 t, %1; cvt.u32.u64 %0, t; }" : "=r"(a) : "l"(p));
    return a;
}
__device__ __forceinline__ float fast_exp2(float x) {
    float y;
    asm("ex2.approx.ftz.f32 %0, %1;" : "=f"(y) : "f"(x));
    return y;
}
__device__ __forceinline__ void cp_async16(uint32_t saddr, const void* gptr) {
    asm volatile("cp.async.cg.shared.global [%0], [%1], 16;" :: "r"(saddr), "l"(gptr) : "memory");
}
#define CP_COMMIT() asm volatile("cp.async.commit_group;" ::: "memory")
#define CP_WAIT0()  asm volatile("cp.async.wait_group 0;" ::: "memory")
#define CP_WAIT1()  asm volatile("cp.async.wait_group 1;" ::: "memory")

__device__ __forceinline__ void ldsm_x4(uint32_t* r, uint32_t addr) {
    asm volatile("ldmatrix.sync.aligned.m8n8.x4.shared.b16 {%0,%1,%2,%3}, [%4];"
        : "=r"(r[0]), "=r"(r[1]), "=r"(r[2]), "=r"(r[3]) : "r"(addr));
}
__device__ __forceinline__ void ldsm_x4_t(uint32_t* r, uint32_t addr) {
    asm volatile("ldmatrix.sync.aligned.m8n8.x4.trans.shared.b16 {%0,%1,%2,%3}, [%4];"
        : "=r"(r[0]), "=r"(r[1]), "=r"(r[2]), "=r"(r[3]) : "r"(addr));
}

// mma m16n8k16 fp16 inputs, fp32 accum
__device__ __forceinline__ void mma_f16(float* c, const uint32_t* a, uint32_t b0, uint32_t b1) {
    asm volatile(
        "mma.sync.aligned.m16n8k16.row.col.f32.f16.f16.f32 "
        "{%0,%1,%2,%3}, {%4,%5,%6,%7}, {%8,%9}, {%0,%1,%2,%3};"
        : "+f"(c[0]), "+f"(c[1]), "+f"(c[2]), "+f"(c[3])
        : "r"(a[0]), "r"(a[1]), "r"(a[2]), "r"(a[3]), "r"(b0), "r"(b1));
}

// ===========================================================================
// prep kernels
// ===========================================================================
__global__ void f2h_k(const float* __restrict__ in, __half* __restrict__ out, int n4)
{
    int i = blockIdx.x * blockDim.x + threadIdx.x;
    if (i < n4) {
        float4 v = ((const float4*)in)[i];
        __half2 h0 = __floats2half2_rn(v.x, v.y);
        __half2 h1 = __floats2half2_rn(v.z, v.w);
        ((__half2*)out)[2 * i]     = h0;
        ((__half2*)out)[2 * i + 1] = h1;
    }
}

// out[C][R] = half(in[R][C])
__global__ void transpose_h(const float* __restrict__ in, __half* __restrict__ out, int R, int C)
{
    __shared__ float t[32][33];
    int bx = blockIdx.x * 32, by = blockIdx.y * 32;
    int x = bx + threadIdx.x;
#pragma unroll
    for (int j = 0; j < 32; j += 8) {
        int y = by + threadIdx.y + j;
        t[threadIdx.y + j][threadIdx.x] = in[(size_t)y * C + x];
    }
    __syncthreads();
    int x2 = by + threadIdx.x;
#pragma unroll
    for (int j = 0; j < 32; j += 8) {
        int y2 = bx + threadIdx.y + j;
        out[(size_t)y2 * R + x2] = __float2half_rn(t[threadIdx.x][threadIdx.y + j]);
    }
}

// ===========================================================================
// fp16 mma GEMM: C[M,N] = A[M,K] @ Bt[N,K]^T (half inputs, row-major)
// 128x128 CTA tile, BK=32, 256 thr (8 warps 2x4, 64x32 warp tiles),
// double-buffered cp.async, ldmatrix fragment loads.
// OUT_HALF: write half (else float).
// ===========================================================================
template<bool OUT_HALF>
__global__ __launch_bounds__(256)
void gemm_h(const __half* __restrict__ A, const __half* __restrict__ Bt,
            void* __restrict__ Cv, int M, int N, int K)
{
    __shared__ __half As[2][128][40];   // 40-half stride: conflict-free ldmatrix
    __shared__ __half Bs[2][128][40];

    const int tid  = threadIdx.x;
    const int wid  = tid >> 5;
    const int lane = tid & 31;
    const int g4   = lane >> 2;
    const int l4   = lane & 3;
    const int wm   = (wid >> 2) * 64;
    const int wn   = (wid & 3) * 32;
    const int bm   = blockIdx.y * 128;
    const int bn   = blockIdx.x * 128;

    // ldmatrix per-lane address components
    const int arow = wm + (lane & 7) + ((lane >> 3) & 1) * 8;   // + mi*16
    const int acol = (lane >> 4) * 8;                           // + kb*16
    const int brow = wn + (lane & 7) + (lane >> 4) * 8;         // + p*16
    const int bcol = ((lane >> 3) & 1) * 8;                     // + kb*16

    float acc[4][4][4];
#pragma unroll
    for (int mi = 0; mi < 4; mi++)
#pragma unroll
        for (int ni = 0; ni < 4; ni++)
#pragma unroll
            for (int r = 0; r < 4; r++) acc[mi][ni][r] = 0.f;

    const int KC = K >> 5;   // BK=32 chunks

    auto load_stage = [&](int s, int k0) {
#pragma unroll
        for (int u = 0; u < 2; u++) {
            int ch  = tid * 2 + u;          // 0..511
            int row = ch >> 2;              // 0..127
            int j   = ch & 3;               // 16B chunk (8 halves)
            cp_async16(smem_u32(&As[s][row][j * 8]), A  + (size_t)(bm + row) * K + k0 + j * 8);
            cp_async16(smem_u32(&Bs[s][row][j * 8]), Bt + (size_t)(bn + row) * K + k0 + j * 8);
        }
        CP_COMMIT();
    };

    load_stage(0, 0);
    CP_WAIT0();
    __syncthreads();

    for (int i = 0; i < KC; i++) {
        const int s = i & 1;
        if (i + 1 < KC) load_stage(s ^ 1, (i + 1) << 5);

#pragma unroll
        for (int kb = 0; kb < 2; kb++) {
            uint32_t a[4][4];
#pragma unroll
            for (int mi = 0; mi < 4; mi++)
                ldsm_x4(a[mi], smem_u32(&As[s][arow + mi * 16][acol + kb * 16]));
            uint32_t b[2][4];
#pragma unroll
            for (int p = 0; p < 2; p++)
                ldsm_x4(b[p], smem_u32(&Bs[s][brow + p * 16][bcol + kb * 16]));
#pragma unroll
            for (int mi = 0; mi < 4; mi++)
#pragma unroll
                for (int ni = 0; ni < 4; ni++)
                    mma_f16(acc[mi][ni], a[mi],
                            b[ni >> 1][2 * (ni & 1)], b[ni >> 1][2 * (ni & 1) + 1]);
        }

        if (i + 1 < KC) CP_WAIT0();
        __syncthreads();
    }

    // epilogue
#pragma unroll
    for (int mi = 0; mi < 4; mi++) {
        int r0 = bm + wm + mi * 16 + g4;
#pragma unroll
        for (int ni = 0; ni < 4; ni++) {
            int c0 = bn + wn + ni * 8 + 2 * l4;
            if (OUT_HALF) {
                __half* Ch = (__half*)Cv;
                *(__half2*)&Ch[(size_t)r0 * N + c0] =
                    __floats2half2_rn(acc[mi][ni][0], acc[mi][ni][1]);
                *(__half2*)&Ch[(size_t)(r0 + 8) * N + c0] =
                    __floats2half2_rn(acc[mi][ni][2], acc[mi][ni][3]);
            } else {
                float* Cf = (float*)Cv;
                *(float2*)&Cf[(size_t)r0 * N + c0]       = make_float2(acc[mi][ni][0], acc[mi][ni][1]);
                *(float2*)&Cf[(size_t)(r0 + 8) * N + c0] = make_float2(acc[mi][ni][2], acc[mi][ni][3]);
            }
        }
    }
}

// ===========================================================================
// fp16 tensor-core flash attention.
// Block = 128 queries x (b,h). 256 thr / 8 warps; warp owns 16 q rows.
// K/V tiles of 64, double-buffered cp.async. Q fragments hoisted to regs.
// ldmatrix for K (B-op), P (A-op), V (B-op, .trans). Softmax in fp32/base-2.
// ===========================================================================
struct AttnSmemH {
    __half Qs[128][72];
    __half Ks[2][64][72];
    __half Vs[2][64][72];
    __half Ps[128][72];
};
#define ATTN_SMEM_BYTES ((int)sizeof(AttnSmemH))

__global__ __launch_bounds__(256)
void attn_h(const __half* __restrict__ qkv, __half* __restrict__ out)
{
    extern __shared__ char sm_raw[];
    AttnSmemH& S = *reinterpret_cast<AttnSmemH*>(sm_raw);

    const int tid  = threadIdx.x;
    const int wid  = tid >> 5;
    const int lane = tid & 31;
    const int g4   = lane >> 2;
    const int l4   = lane & 3;
    const int q0   = blockIdx.x * 128;
    const int h    = blockIdx.y;
    const int b    = blockIdx.z;
    const int qrow = wid * 16;

    const __half* base = qkv + (size_t)b * SEQ * DIM3 + h * HDIM;
    const __half* qg = base;
    const __half* kg = base + DIM;
    const __half* vg = base + 2 * DIM;

    // A-fragment lane addressing (Q and P): row += (l&7) + ((l>>3)&1)*8, col += (l>>4)*8
    const int frow = (lane & 7) + ((lane >> 3) & 1) * 8;
    const int fcol = (lane >> 4) * 8;
    // K B-fragment: t-row = p*16 + (l&7) + (l>>4)*8 ; d-col = kb*16 + ((l>>3)&1)*8
    const int krow = (lane & 7) + (lane >> 4) * 8;
    const int kcol = ((lane >> 3) & 1) * 8;
    // V B-fragment (.trans): t-row = kb*16 + (l&7) + ((l>>3)&1)*8 ; d-col = p*16 + (l>>4)*8
    const int vrow = (lane & 7) + ((lane >> 3) & 1) * 8;
    const int vcol = (lane >> 4) * 8;

    // ---- Q tile load (128 x 64 halves) ----
#pragma unroll
    for (int u = 0; u < 4; u++) {
        int ch = tid + u * 256;          // 0..1023
        int r  = ch >> 3;                // 0..127
        int j  = ch & 7;                 // 8 chunks of 8 halves
        cp_async16(smem_u32(&S.Qs[r][j * 8]), qg + (size_t)(q0 + r) * DIM3 + j * 8);
    }
    CP_COMMIT();

    auto load_kv = [&](int s, int t0) {
#pragma unroll
        for (int u = 0; u < 2; u++) {
            int ch = tid + u * 256;      // 0..511
            int r  = ch >> 3;            // 0..63
            int j  = ch & 7;
            cp_async16(smem_u32(&S.Ks[s][r][j * 8]), kg + (size_t)(t0 + r) * DIM3 + j * 8);
            cp_async16(smem_u32(&S.Vs[s][r][j * 8]), vg + (size_t)(t0 + r) * DIM3 + j * 8);
        }
        CP_COMMIT();
    };

    load_kv(0, 0);
    CP_WAIT0();
    __syncthreads();

    // ---- hoist Q fragments (warp-invariant across all key tiles) ----
    uint32_t Qf[4][4];
#pragma unroll
    for (int kb = 0; kb < 4; kb++)
        ldsm_x4(Qf[kb], smem_u32(&S.Qs[qrow + frow][fcol + kb * 16]));

    float m2[2] = { -1e30f, -1e30f };
    float l[2]  = { 0.f, 0.f };
    float O[8][4];
#pragma unroll
    for (int ni = 0; ni < 8; ni++)
#pragma unroll
        for (int r = 0; r < 4; r++) O[ni][r] = 0.f;

    const int NT = SEQ / 64;   // 32 key tiles

    for (int it = 0; it < NT; it++) {
        const int s = it & 1;
        if (it + 1 < NT) {
            load_kv(s ^ 1, (it + 1) * 64);
            CP_WAIT1();
        } else {
            CP_WAIT0();
        }
        __syncthreads();

        // ---- QK^T : 16 q-rows x 64 keys ----
        float sreg[8][4];
#pragma unroll
        for (int ni = 0; ni < 8; ni++)
#pragma unroll
            for (int r = 0; r < 4; r++) sreg[ni][r] = 0.f;

#pragma unroll
        for (int kb = 0; kb < 4; kb++) {
#pragma unroll
            for (int p = 0; p < 4; p++) {
                uint32_t kf[4];
                ldsm_x4(kf, smem_u32(&S.Ks[s][p * 16 + krow][kcol + kb * 16]));
                mma_f16(sreg[2 * p],     Qf[kb], kf[0], kf[1]);
                mma_f16(sreg[2 * p + 1], Qf[kb], kf[2], kf[3]);
            }
        }

        // ---- online softmax (base-2) ----
        float mx0 = -1e30f, mx1 = -1e30f;
#pragma unroll
        for (int ni = 0; ni < 8; ni++) {
            sreg[ni][0] *= SCALE_LOG2E; sreg[ni][1] *= SCALE_LOG2E;
            sreg[ni][2] *= SCALE_LOG2E; sreg[ni][3] *= SCALE_LOG2E;
            mx0 = fmaxf(mx0, fmaxf(sreg[ni][0], sreg[ni][1]));
            mx1 = fmaxf(mx1, fmaxf(sreg[ni][2], sreg[ni][3]));
        }
        mx0 = fmaxf(mx0, __shfl_xor_sync(0xffffffffu, mx0, 1));
        mx0 = fmaxf(mx0, __shfl_xor_sync(0xffffffffu, mx0, 2));
        mx1 = fmaxf(mx1, __shfl_xor_sync(0xffffffffu, mx1, 1));
        mx1 = fmaxf(mx1, __shfl_xor_sync(0xffffffffu, mx1, 2));

        const float mn0 = fmaxf(m2[0], mx0);
        const float mn1 = fmaxf(m2[1], mx1);
        const float al0 = fast_exp2(m2[0] - mn0);
        const float al1 = fast_exp2(m2[1] - mn1);

        float s0 = 0.f, s1 = 0.f;
#pragma unroll
        for (int ni = 0; ni < 8; ni++) {
            float p0 = fast_exp2(sreg[ni][0] - mn0);
            float p1 = fast_exp2(sreg[ni][1] - mn0);
            float p2 = fast_exp2(sreg[ni][2] - mn1);
            float p3 = fast_exp2(sreg[ni][3] - mn1);
            s0 += p0 + p1;
            s1 += p2 + p3;
            const int col = ni * 8 + 2 * l4;
            *(__half2*)&S.Ps[qrow + g4    ][col] = __floats2half2_rn(p0, p1);
            *(__half2*)&S.Ps[qrow + g4 + 8][col] = __floats2half2_rn(p2, p3);
        }
        s0 += __shfl_xor_sync(0xffffffffu, s0, 1);
        s0 += __shfl_xor_sync(0xffffffffu, s0, 2);
        s1 += __shfl_xor_sync(0xffffffffu, s1, 1);
        s1 += __shfl_xor_sync(0xffffffffu, s1, 2);

        l[0] = l[0] * al0 + s0;
        l[1] = l[1] * al1 + s1;
        m2[0] = mn0;
        m2[1] = mn1;

#pragma unroll
        for (int ni = 0; ni < 8; ni++) {
            O[ni][0] *= al0; O[ni][1] *= al0;
            O[ni][2] *= al1; O[ni][3] *= al1;
        }
        __syncwarp();

        // ---- P @ V ----
#pragma unroll
        for (int kb = 0; kb < 4; kb++) {
            uint32_t Pf[4];
            ldsm_x4(Pf, smem_u32(&S.Ps[qrow + frow][fcol + kb * 16]));
#pragma unroll
            for (int p = 0; p < 4; p++) {
                uint32_t vf[4];
                ldsm_x4_t(vf, smem_u32(&S.Vs[s][kb * 16 + vrow][vcol + p * 16]));
                mma_f16(O[2 * p],     Pf, vf[0], vf[1]);
                mma_f16(O[2 * p + 1], Pf, vf[2], vf[3]);
            }
        }
        __syncthreads();
    }

    // ---- normalize + store (half, feeds GEMM2) ----
    const float inv0 = 1.f / l[0];
    const float inv1 = 1.f / l[1];
    __half* ob = out + (size_t)b * SEQ * DIM + h * HDIM;
    const int r0 = q0 + qrow + g4;
#pragma unroll
    for (int ni = 0; ni < 8; ni++) {
        const int col = ni * 8 + 2 * l4;
        *(__half2*)&ob[(size_t)r0 * DIM + col] =
            __floats2half2_rn(O[ni][0] * inv0, O[ni][1] * inv0);
        *(__half2*)&ob[(size_t)(r0 + 8) * DIM + col] =
            __floats2half2_rn(O[ni][2] * inv1, O[ni][3] * inv1);
    }
}

// ===========================================================================
extern "C" void kernel_launch(void* const* d_in, const int* in_sizes, int n_in,
                              void* d_out, int out_size)
{
    const float* x     = (const float*)d_in[0];   // [B,S,DIM]
    const float* Wqkv  = (const float*)d_in[1];   // [DIM, 3*DIM]
    const float* Wproj = (const float*)d_in[2];   // [DIM, DIM]
    float*       outp  = (float*)d_out;           // [B,S,DIM]

    __half* qkvh;   cudaGetSymbolAddress((void**)&qkvh,   g_qkvh);
    __half* attnh;  cudaGetSymbolAddress((void**)&attnh,  g_attnh);
    __half* xh;     cudaGetSymbolAddress((void**)&xh,     g_xh);
    __half* wqkvT;  cudaGetSymbolAddress((void**)&wqkvT,  g_wqkvTh);
    __half* wprojT; cudaGetSymbolAddress((void**)&wprojT, g_wprojTh);

    static bool attr_set = false;
    if (!attr_set) {
        cudaFuncSetAttribute(attn_h, cudaFuncAttributeMaxDynamicSharedMemorySize,
                             ATTN_SMEM_BYTES);
        attr_set = true;
    }

    // 0) operand prep: fp32 -> fp16 (+ weight transposes)
    {
        int n4 = MROWS * DIM / 4;
        f2h_k<<<(n4 + 255) / 256, 256>>>(x, xh, n4);
        transpose_h<<<dim3(DIM3 / 32, DIM / 32), dim3(32, 8)>>>(Wqkv,  wqkvT,  DIM, DIM3);
        transpose_h<<<dim3(DIM  / 32, DIM / 32), dim3(32, 8)>>>(Wproj, wprojT, DIM, DIM);
    }

    // 1) qkv = x @ Wqkv   (half out)
    gemm_h<true><<<dim3(DIM3 / 128, MROWS / 128), 256>>>(xh, wqkvT, qkvh, MROWS, DIM3, DIM);

    // 2) attention (fp16 tensor core)
    attn_h<<<dim3(SEQ / 128, NHEAD, BATCH), 256, ATTN_SMEM_BYTES>>>(qkvh, attnh);

    // 3) out = attn @ Wproj (float out)
    gemm_h<false><<<dim3(DIM / 128, MROWS / 128), 256>>>(attnh, wprojT, outp, MROWS, DIM, DIM);
}

// round 6
// speedup vs baseline: 6.6827x; 1.0859x over previous
#include <cuda_runtime.h>
#include <cuda_fp16.h>
#include <math.h>
#include <stdint.h>

// Problem dims (fixed)
#define BATCH 2
#define SEQ   2048
#define DIM   1024
#define NHEAD 16
#define HDIM  64
#define DIM3  (3*DIM)
#define MROWS (BATCH*SEQ)      // 4096
#define SCALE_LOG2E 0.1803368801111729f   // 64^-0.5 * log2(e)

// Scratch (device globals; allocation-free rule)
__device__ __half g_qkvh  [ (size_t)BATCH * SEQ * DIM3 ];
__device__ __half g_attnh [ (size_t)BATCH * SEQ * DIM  ];
__device__ __half g_xh    [ (size_t)MROWS * DIM ];
__device__ __half g_wqkvTh[ (size_t)DIM3 * DIM ];
__device__ __half g_wprojTh[ (size_t)DIM * DIM ];

// ===========================================================================
// helpers
// ===========================================================================
__device__ __forceinline__ uint32_t smem_u32(const void* p) {
    uint32_t a;
    asm("{ .reg .u64 t; cvta.to.shared.u64 t, %1; cvt.u32.u64 %0, t; }" : "=r"(a) : "l"(p));
    return a;
}
__device__ __forceinline__ float fast_exp2(float x) {
    float y;
    asm("ex2.approx.ftz.f32 %0, %1;" : "=f"(y) : "f"(x));
    return y;
}
__device__ __forceinline__ void cp_async16(uint32_t saddr, const void* gptr) {
    asm volatile("cp.async.cg.shared.global [%0], [%1], 16;" :: "r"(saddr), "l"(gptr) : "memory");
}
#define CP_COMMIT() asm volatile("cp.async.commit_group;" ::: "memory")
#define CP_WAIT0()  asm volatile("cp.async.wait_group 0;" ::: "memory")
#define CP_WAIT1()  asm volatile("cp.async.wait_group 1;" ::: "memory")

__device__ __forceinline__ void ldsm_x4(uint32_t* r, uint32_t addr) {
    asm volatile("ldmatrix.sync.aligned.m8n8.x4.shared.b16 {%0,%1,%2,%3}, [%4];"
        : "=r"(r[0]), "=r"(r[1]), "=r"(r[2]), "=r"(r[3]) : "r"(addr));
}
__device__ __forceinline__ void ldsm_x4_t(uint32_t* r, uint32_t addr) {
    asm volatile("ldmatrix.sync.aligned.m8n8.x4.trans.shared.b16 {%0,%1,%2,%3}, [%4];"
        : "=r"(r[0]), "=r"(r[1]), "=r"(r[2]), "=r"(r[3]) : "r"(addr));
}

// mma m16n8k16 fp16 inputs, fp32 accum
__device__ __forceinline__ void mma_f16(float* c, const uint32_t* a, uint32_t b0, uint32_t b1) {
    asm volatile(
        "mma.sync.aligned.m16n8k16.row.col.f32.f16.f16.f32 "
        "{%0,%1,%2,%3}, {%4,%5,%6,%7}, {%8,%9}, {%0,%1,%2,%3};"
        : "+f"(c[0]), "+f"(c[1]), "+f"(c[2]), "+f"(c[3])
        : "r"(a[0]), "r"(a[1]), "r"(a[2]), "r"(a[3]), "r"(b0), "r"(b1));
}
__device__ __forceinline__ uint32_t h2_pack(float a, float b) {
    __half2 h = __floats2half2_rn(a, b);
    return *reinterpret_cast<uint32_t*>(&h);
}

// ===========================================================================
// prep kernels
// ===========================================================================
__global__ void f2h_k(const float* __restrict__ in, __half* __restrict__ out, int n4)
{
    int i = blockIdx.x * blockDim.x + threadIdx.x;
    if (i < n4) {
        float4 v = ((const float4*)in)[i];
        ((__half2*)out)[2 * i]     = __floats2half2_rn(v.x, v.y);
        ((__half2*)out)[2 * i + 1] = __floats2half2_rn(v.z, v.w);
    }
}

// out[C][R] = half(in[R][C])
__global__ void transpose_h(const float* __restrict__ in, __half* __restrict__ out, int R, int C)
{
    __shared__ float t[32][33];
    int bx = blockIdx.x * 32, by = blockIdx.y * 32;
    int x = bx + threadIdx.x;
#pragma unroll
    for (int j = 0; j < 32; j += 8) {
        int y = by + threadIdx.y + j;
        t[threadIdx.y + j][threadIdx.x] = in[(size_t)y * C + x];
    }
    __syncthreads();
    int x2 = by + threadIdx.x;
#pragma unroll
    for (int j = 0; j < 32; j += 8) {
        int y2 = bx + threadIdx.y + j;
        out[(size_t)y2 * R + x2] = __float2half_rn(t[threadIdx.x][threadIdx.y + j]);
    }
}

// ===========================================================================
// fp16 mma GEMM: C[M,N] = A[M,K] @ Bt[N,K]^T (half inputs, row-major)
// 128x128 CTA tile, BK=32, 256 thr (8 warps 2x4, 64x32 warp tiles),
// 3-stage cp.async pipeline, one barrier per chunk, ldmatrix fragment loads.
// ===========================================================================
struct GSmem {
    __half As[3][128][40];
    __half Bs[3][128][40];
};
#define GEMM_SMEM_BYTES ((int)sizeof(GSmem))

template<bool OUT_HALF>
__global__ __launch_bounds__(256, 2)
void gemm_h(const __half* __restrict__ A, const __half* __restrict__ Bt,
            void* __restrict__ Cv, int M, int N, int K)
{
    extern __shared__ char sm_raw[];
    GSmem& S = *reinterpret_cast<GSmem*>(sm_raw);

    const int tid  = threadIdx.x;
    const int wid  = tid >> 5;
    const int lane = tid & 31;
    const int g4   = lane >> 2;
    const int l4   = lane & 3;
    const int wm   = (wid >> 2) * 64;
    const int wn   = (wid & 3) * 32;
    const int bm   = blockIdx.y * 128;
    const int bn   = blockIdx.x * 128;

    const int arow = wm + (lane & 7) + ((lane >> 3) & 1) * 8;   // + mi*16
    const int acol = (lane >> 4) * 8;                           // + kb*16
    const int brow = wn + (lane & 7) + (lane >> 4) * 8;         // + p*16
    const int bcol = ((lane >> 3) & 1) * 8;                     // + kb*16

    float acc[4][4][4];
#pragma unroll
    for (int mi = 0; mi < 4; mi++)
#pragma unroll
        for (int ni = 0; ni < 4; ni++)
#pragma unroll
            for (int r = 0; r < 4; r++) acc[mi][ni][r] = 0.f;

    const int KC = K >> 5;   // BK=32 chunks

    auto load_stage = [&](int st, int k0) {
#pragma unroll
        for (int u = 0; u < 2; u++) {
            int ch  = tid * 2 + u;          // 0..511
            int row = ch >> 2;              // 0..127
            int j   = ch & 3;               // 16B chunk (8 halves)
            cp_async16(smem_u32(&S.As[st][row][j * 8]), A  + (size_t)(bm + row) * K + k0 + j * 8);
            cp_async16(smem_u32(&S.Bs[st][row][j * 8]), Bt + (size_t)(bn + row) * K + k0 + j * 8);
        }
        CP_COMMIT();
    };

    load_stage(0, 0);
    load_stage(1, 32);

    int st = 0;
    for (int i = 0; i < KC; i++) {
        if (i + 1 < KC) { CP_WAIT1(); } else { CP_WAIT0(); }
        __syncthreads();
        if (i + 2 < KC) load_stage((st + 2) % 3, (i + 2) << 5);

#pragma unroll
        for (int kb = 0; kb < 2; kb++) {
            uint32_t a[4][4];
#pragma unroll
            for (int mi = 0; mi < 4; mi++)
                ldsm_x4(a[mi], smem_u32(&S.As[st][arow + mi * 16][acol + kb * 16]));
            uint32_t b[2][4];
#pragma unroll
            for (int p = 0; p < 2; p++)
                ldsm_x4(b[p], smem_u32(&S.Bs[st][brow + p * 16][bcol + kb * 16]));
#pragma unroll
            for (int mi = 0; mi < 4; mi++)
#pragma unroll
                for (int ni = 0; ni < 4; ni++)
                    mma_f16(acc[mi][ni], a[mi],
                            b[ni >> 1][2 * (ni & 1)], b[ni >> 1][2 * (ni & 1) + 1]);
        }
        st = (st + 1) % 3;
    }

    // epilogue
#pragma unroll
    for (int mi = 0; mi < 4; mi++) {
        int r0 = bm + wm + mi * 16 + g4;
#pragma unroll
        for (int ni = 0; ni < 4; ni++) {
            int c0 = bn + wn + ni * 8 + 2 * l4;
            if (OUT_HALF) {
                __half* Ch = (__half*)Cv;
                *(__half2*)&Ch[(size_t)r0 * N + c0] =
                    __floats2half2_rn(acc[mi][ni][0], acc[mi][ni][1]);
                *(__half2*)&Ch[(size_t)(r0 + 8) * N + c0] =
                    __floats2half2_rn(acc[mi][ni][2], acc[mi][ni][3]);
            } else {
                float* Cf = (float*)Cv;
                *(float2*)&Cf[(size_t)r0 * N + c0]       = make_float2(acc[mi][ni][0], acc[mi][ni][1]);
                *(float2*)&Cf[(size_t)(r0 + 8) * N + c0] = make_float2(acc[mi][ni][2], acc[mi][ni][3]);
            }
        }
    }
}

// ===========================================================================
// fp16 tensor-core flash attention. P kept entirely in registers:
// QK^T C-fragment (m16n8) repacks directly into PV A-fragment (m16k16).
// Block = 128 queries x (b,h). 256 thr / 8 warps; warp owns 16 q rows.
// K/V tiles of 64, double-buffered cp.async, ONE barrier per tile.
// ===========================================================================
struct AttnSmemH {
    __half Qs[128][72];
    __half Ks[2][64][72];
    __half Vs[2][64][72];
};
#define ATTN_SMEM_BYTES ((int)sizeof(AttnSmemH))

__global__ __launch_bounds__(256, 2)
void attn_h(const __half* __restrict__ qkv, __half* __restrict__ out)
{
    extern __shared__ char sm_raw[];
    AttnSmemH& S = *reinterpret_cast<AttnSmemH*>(sm_raw);

    const int tid  = threadIdx.x;
    const int wid  = tid >> 5;
    const int lane = tid & 31;
    const int g4   = lane >> 2;
    const int l4   = lane & 3;
    const int q0   = blockIdx.x * 128;
    const int h    = blockIdx.y;
    const int b    = blockIdx.z;
    const int qrow = wid * 16;

    const __half* base = qkv + (size_t)b * SEQ * DIM3 + h * HDIM;
    const __half* qg = base;
    const __half* kg = base + DIM;
    const __half* vg = base + 2 * DIM;

    const int frow = (lane & 7) + ((lane >> 3) & 1) * 8;   // A-frag row offset
    const int fcol = (lane >> 4) * 8;                      // A-frag col offset
    const int krow = (lane & 7) + (lane >> 4) * 8;         // K B-frag row
    const int kcol = ((lane >> 3) & 1) * 8;                // K B-frag col
    const int vrow = (lane & 7) + ((lane >> 3) & 1) * 8;   // V B-frag (.trans) row
    const int vcol = (lane >> 4) * 8;                      // V B-frag col

    // ---- Q tile load (128 x 64 halves) ----
#pragma unroll
    for (int u = 0; u < 4; u++) {
        int ch = tid + u * 256;
        int r  = ch >> 3;
        int j  = ch & 7;
        cp_async16(smem_u32(&S.Qs[r][j * 8]), qg + (size_t)(q0 + r) * DIM3 + j * 8);
    }
    CP_COMMIT();

    auto load_kv = [&](int s, int t0) {
#pragma unroll
        for (int u = 0; u < 2; u++) {
            int ch = tid + u * 256;
            int r  = ch >> 3;
            int j  = ch & 7;
            cp_async16(smem_u32(&S.Ks[s][r][j * 8]), kg + (size_t)(t0 + r) * DIM3 + j * 8);
            cp_async16(smem_u32(&S.Vs[s][r][j * 8]), vg + (size_t)(t0 + r) * DIM3 + j * 8);
        }
        CP_COMMIT();
    };

    load_kv(0, 0);
    CP_WAIT0();
    __syncthreads();

    // ---- hoist Q fragments (warp-invariant across all key tiles) ----
    uint32_t Qf[4][4];
#pragma unroll
    for (int kb = 0; kb < 4; kb++)
        ldsm_x4(Qf[kb], smem_u32(&S.Qs[qrow + frow][fcol + kb * 16]));

    float m2[2] = { -1e30f, -1e30f };
    float l[2]  = { 0.f, 0.f };
    float O[8][4];
#pragma unroll
    for (int ni = 0; ni < 8; ni++)
#pragma unroll
        for (int r = 0; r < 4; r++) O[ni][r] = 0.f;

    const int NT = SEQ / 64;

    for (int it = 0; it < NT; it++) {
        const int s = it & 1;
        if (it + 1 < NT) load_kv(s ^ 1, (it + 1) * 64);

        // ---- QK^T : 16 q-rows x 64 keys ----
        float sreg[8][4];
#pragma unroll
        for (int ni = 0; ni < 8; ni++)
#pragma unroll
            for (int r = 0; r < 4; r++) sreg[ni][r] = 0.f;

#pragma unroll
        for (int kb = 0; kb < 4; kb++) {
#pragma unroll
            for (int p = 0; p < 4; p++) {
                uint32_t kf[4];
                ldsm_x4(kf, smem_u32(&S.Ks[s][p * 16 + krow][kcol + kb * 16]));
                mma_f16(sreg[2 * p],     Qf[kb], kf[0], kf[1]);
                mma_f16(sreg[2 * p + 1], Qf[kb], kf[2], kf[3]);
            }
        }

        // ---- online softmax (base-2) ----
        float mx0 = -1e30f, mx1 = -1e30f;
#pragma unroll
        for (int ni = 0; ni < 8; ni++) {
            sreg[ni][0] *= SCALE_LOG2E; sreg[ni][1] *= SCALE_LOG2E;
            sreg[ni][2] *= SCALE_LOG2E; sreg[ni][3] *= SCALE_LOG2E;
            mx0 = fmaxf(mx0, fmaxf(sreg[ni][0], sreg[ni][1]));
            mx1 = fmaxf(mx1, fmaxf(sreg[ni][2], sreg[ni][3]));
        }
        mx0 = fmaxf(mx0, __shfl_xor_sync(0xffffffffu, mx0, 1));
        mx0 = fmaxf(mx0, __shfl_xor_sync(0xffffffffu, mx0, 2));
        mx1 = fmaxf(mx1, __shfl_xor_sync(0xffffffffu, mx1, 1));
        mx1 = fmaxf(mx1, __shfl_xor_sync(0xffffffffu, mx1, 2));

        const float mn0 = fmaxf(m2[0], mx0);
        const float mn1 = fmaxf(m2[1], mx1);
        const float al0 = fast_exp2(m2[0] - mn0);
        const float al1 = fast_exp2(m2[1] - mn1);

        // ---- exp + pack P directly into PV A-fragments ----
        uint32_t Pf[4][4];
        float s0 = 0.f, s1 = 0.f;
#pragma unroll
        for (int ni = 0; ni < 8; ni++) {
            float p0 = fast_exp2(sreg[ni][0] - mn0);
            float p1 = fast_exp2(sreg[ni][1] - mn0);
            float p2 = fast_exp2(sreg[ni][2] - mn1);
            float p3 = fast_exp2(sreg[ni][3] - mn1);
            s0 += p0 + p1;
            s1 += p2 + p3;
            Pf[ni >> 1][2 * (ni & 1)]     = h2_pack(p0, p1);
            Pf[ni >> 1][2 * (ni & 1) + 1] = h2_pack(p2, p3);
        }
        s0 += __shfl_xor_sync(0xffffffffu, s0, 1);
        s0 += __shfl_xor_sync(0xffffffffu, s0, 2);
        s1 += __shfl_xor_sync(0xffffffffu, s1, 1);
        s1 += __shfl_xor_sync(0xffffffffu, s1, 2);

        l[0] = l[0] * al0 + s0;
        l[1] = l[1] * al1 + s1;
        m2[0] = mn0;
        m2[1] = mn1;

#pragma unroll
        for (int ni = 0; ni < 8; ni++) {
            O[ni][0] *= al0; O[ni][1] *= al0;
            O[ni][2] *= al1; O[ni][3] *= al1;
        }

        // ---- P @ V ----
#pragma unroll
        for (int kb = 0; kb < 4; kb++) {
#pragma unroll
            for (int p = 0; p < 4; p++) {
                uint32_t vf[4];
                ldsm_x4_t(vf, smem_u32(&S.Vs[s][kb * 16 + vrow][vcol + p * 16]));
                mma_f16(O[2 * p],     Pf[kb], vf[0], vf[1]);
                mma_f16(O[2 * p + 1], Pf[kb], vf[2], vf[3]);
            }
        }

        if (it + 1 < NT) CP_WAIT0();
        __syncthreads();
    }

    // ---- normalize + store (half, feeds GEMM2) ----
    const float inv0 = 1.f / l[0];
    const float inv1 = 1.f / l[1];
    __half* ob = out + (size_t)b * SEQ * DIM + h * HDIM;
    const int r0 = q0 + qrow + g4;
#pragma unroll
    for (int ni = 0; ni < 8; ni++) {
        const int col = ni * 8 + 2 * l4;
        *(__half2*)&ob[(size_t)r0 * DIM + col] =
            __floats2half2_rn(O[ni][0] * inv0, O[ni][1] * inv0);
        *(__half2*)&ob[(size_t)(r0 + 8) * DIM + col] =
            __floats2half2_rn(O[ni][2] * inv1, O[ni][3] * inv1);
    }
}

// ===========================================================================
extern "C" void kernel_launch(void* const* d_in, const int* in_sizes, int n_in,
                              void* d_out, int out_size)
{
    const float* x     = (const float*)d_in[0];
    const float* Wqkv  = (const float*)d_in[1];
    const float* Wproj = (const float*)d_in[2];
    float*       outp  = (float*)d_out;

    __half* qkvh;   cudaGetSymbolAddress((void**)&qkvh,   g_qkvh);
    __half* attnh;  cudaGetSymbolAddress((void**)&attnh,  g_attnh);
    __half* xh;     cudaGetSymbolAddress((void**)&xh,     g_xh);
    __half* wqkvT;  cudaGetSymbolAddress((void**)&wqkvT,  g_wqkvTh);
    __half* wprojT; cudaGetSymbolAddress((void**)&wprojT, g_wprojTh);

    static bool attr_set = false;
    if (!attr_set) {
        cudaFuncSetAttribute(attn_h, cudaFuncAttributeMaxDynamicSharedMemorySize,
                             ATTN_SMEM_BYTES);
        cudaFuncSetAttribute(gemm_h<true>, cudaFuncAttributeMaxDynamicSharedMemorySize,
                             GEMM_SMEM_BYTES);
        cudaFuncSetAttribute(gemm_h<false>, cudaFuncAttributeMaxDynamicSharedMemorySize,
                             GEMM_SMEM_BYTES);
        attr_set = true;
    }

    // 0) operand prep: fp32 -> fp16 (+ weight transposes)
    {
        int n4 = MROWS * DIM / 4;
        f2h_k<<<(n4 + 255) / 256, 256>>>(x, xh, n4);
        transpose_h<<<dim3(DIM3 / 32, DIM / 32), dim3(32, 8)>>>(Wqkv,  wqkvT,  DIM, DIM3);
        transpose_h<<<dim3(DIM  / 32, DIM / 32), dim3(32, 8)>>>(Wproj, wprojT, DIM, DIM);
    }

    // 1) qkv = x @ Wqkv   (half out)
    gemm_h<true><<<dim3(DIM3 / 128, MROWS / 128), 256, GEMM_SMEM_BYTES>>>(xh, wqkvT, qkvh, MROWS, DIM3, DIM);

    // 2) attention (fp16 tensor core, register-resident P)
    attn_h<<<dim3(SEQ / 128, NHEAD, BATCH), 256, ATTN_SMEM_BYTES>>>(qkvh, attnh);

    // 3) out = attn @ Wproj (float out)
    gemm_h<false><<<dim3(DIM / 128, MROWS / 128), 256, GEMM_SMEM_BYTES>>>(attnh, wprojT, outp, MROWS, DIM, DIM);
}

// round 7
// speedup vs baseline: 7.3911x; 1.1060x over previous
#include <cuda_runtime.h>
#include <cuda_fp16.h>
#include <math.h>
#include <stdint.h>

// Problem dims (fixed)
#define BATCH 2
#define SEQ   2048
#define DIM   1024
#define NHEAD 16
#define HDIM  64
#define DIM3  (3*DIM)
#define MROWS (BATCH*SEQ)      // 4096
#define SCALE_LOG2E 0.1803368801111729f   // 64^-0.5 * log2(e)

// Scratch (device globals; allocation-free rule)
__device__ __half g_qkvh  [ (size_t)BATCH * SEQ * DIM3 ];
__device__ __half g_attnh [ (size_t)BATCH * SEQ * DIM  ];
__device__ __half g_xh    [ (size_t)MROWS * DIM ];
__device__ __half g_wqkvTh[ (size_t)DIM3 * DIM ];
__device__ __half g_wprojTh[ (size_t)DIM * DIM ];

// ===========================================================================
// helpers
// ===========================================================================
__device__ __forceinline__ uint32_t smem_u32(const void* p) {
    uint32_t a;
    asm("{ .reg .u64 t; cvta.to.shared.u64 t, %1; cvt.u32.u64 %0, t; }" : "=r"(a) : "l"(p));
    return a;
}
__device__ __forceinline__ float fast_exp2(float x) {
    float y;
    asm("ex2.approx.ftz.f32 %0, %1;" : "=f"(y) : "f"(x));
    return y;
}
__device__ __forceinline__ void cp_async16(uint32_t saddr, const void* gptr) {
    asm volatile("cp.async.cg.shared.global [%0], [%1], 16;" :: "r"(saddr), "l"(gptr) : "memory");
}
#define CP_COMMIT() asm volatile("cp.async.commit_group;" ::: "memory")
#define CP_WAIT0()  asm volatile("cp.async.wait_group 0;" ::: "memory")
#define CP_WAIT1()  asm volatile("cp.async.wait_group 1;" ::: "memory")

__device__ __forceinline__ void ldsm_x4(uint32_t* r, uint32_t addr) {
    asm volatile("ldmatrix.sync.aligned.m8n8.x4.shared.b16 {%0,%1,%2,%3}, [%4];"
        : "=r"(r[0]), "=r"(r[1]), "=r"(r[2]), "=r"(r[3]) : "r"(addr));
}
__device__ __forceinline__ void ldsm_x4_t(uint32_t* r, uint32_t addr) {
    asm volatile("ldmatrix.sync.aligned.m8n8.x4.trans.shared.b16 {%0,%1,%2,%3}, [%4];"
        : "=r"(r[0]), "=r"(r[1]), "=r"(r[2]), "=r"(r[3]) : "r"(addr));
}

// mma m16n8k16 fp16 inputs, fp32 accum
__device__ __forceinline__ void mma_f16(float* c, const uint32_t* a, uint32_t b0, uint32_t b1) {
    asm volatile(
        "mma.sync.aligned.m16n8k16.row.col.f32.f16.f16.f32 "
        "{%0,%1,%2,%3}, {%4,%5,%6,%7}, {%8,%9}, {%0,%1,%2,%3};"
        : "+f"(c[0]), "+f"(c[1]), "+f"(c[2]), "+f"(c[3])
        : "r"(a[0]), "r"(a[1]), "r"(a[2]), "r"(a[3]), "r"(b0), "r"(b1));
}
__device__ __forceinline__ uint32_t h2_pack(float a, float b) {
    __half2 h = __floats2half2_rn(a, b);
    return *reinterpret_cast<uint32_t*>(&h);
}

// ===========================================================================
// prep kernels
// ===========================================================================
__global__ void f2h_k(const float* __restrict__ in, __half* __restrict__ out, int n4)
{
    int i = blockIdx.x * blockDim.x + threadIdx.x;
    if (i < n4) {
        float4 v = ((const float4*)in)[i];
        ((__half2*)out)[2 * i]     = __floats2half2_rn(v.x, v.y);
        ((__half2*)out)[2 * i + 1] = __floats2half2_rn(v.z, v.w);
    }
}

// out[C][R] = half(in[R][C])
__global__ void transpose_h(const float* __restrict__ in, __half* __restrict__ out, int R, int C)
{
    __shared__ float t[32][33];
    int bx = blockIdx.x * 32, by = blockIdx.y * 32;
    int x = bx + threadIdx.x;
#pragma unroll
    for (int j = 0; j < 32; j += 8) {
        int y = by + threadIdx.y + j;
        t[threadIdx.y + j][threadIdx.x] = in[(size_t)y * C + x];
    }
    __syncthreads();
    int x2 = by + threadIdx.x;
#pragma unroll
    for (int j = 0; j < 32; j += 8) {
        int y2 = bx + threadIdx.y + j;
        out[(size_t)y2 * R + x2] = __float2half_rn(t[threadIdx.x][threadIdx.y + j]);
    }
}

// ===========================================================================
// fp16 mma GEMM: C[M,N] = A[M,K] @ Bt[N,K]^T (half inputs, row-major)
// 128x128 CTA tile, BK=32, 128 thr (4 warps 2x2, 64x64 warp tiles),
// 3-stage cp.async pipeline. Per kb-step: 8 LDSM : 32 MMA.
// ===========================================================================
struct GSmem {
    __half As[3][128][40];
    __half Bs[3][128][40];
};
#define GEMM_SMEM_BYTES ((int)sizeof(GSmem))

template<bool OUT_HALF>
__global__ __launch_bounds__(128, 2)
void gemm_h(const __half* __restrict__ A, const __half* __restrict__ Bt,
            void* __restrict__ Cv, int M, int N, int K)
{
    extern __shared__ char sm_raw[];
    GSmem& S = *reinterpret_cast<GSmem*>(sm_raw);

    const int tid  = threadIdx.x;
    const int wid  = tid >> 5;
    const int lane = tid & 31;
    const int g4   = lane >> 2;
    const int l4   = lane & 3;
    const int wm   = (wid >> 1) * 64;
    const int wn   = (wid & 1) * 64;
    const int bm   = blockIdx.y * 128;
    const int bn   = blockIdx.x * 128;

    const int arow = wm + (lane & 7) + ((lane >> 3) & 1) * 8;   // + mi*16
    const int acol = (lane >> 4) * 8;                           // + kb*16
    const int brow = wn + (lane & 7) + (lane >> 4) * 8;         // + p*16
    const int bcol = ((lane >> 3) & 1) * 8;                     // + kb*16

    float acc[4][8][4];
#pragma unroll
    for (int mi = 0; mi < 4; mi++)
#pragma unroll
        for (int ni = 0; ni < 8; ni++)
#pragma unroll
            for (int r = 0; r < 4; r++) acc[mi][ni][r] = 0.f;

    const int KC = K >> 5;   // BK=32 chunks

    auto load_stage = [&](int st, int k0) {
#pragma unroll
        for (int u = 0; u < 4; u++) {
            int ch  = tid + u * 128;        // 0..511
            int row = ch >> 2;              // 0..127
            int j   = ch & 3;               // 16B chunk (8 halves)
            cp_async16(smem_u32(&S.As[st][row][j * 8]), A  + (size_t)(bm + row) * K + k0 + j * 8);
            cp_async16(smem_u32(&S.Bs[st][row][j * 8]), Bt + (size_t)(bn + row) * K + k0 + j * 8);
        }
        CP_COMMIT();
    };

    load_stage(0, 0);
    load_stage(1, 32);

    int st = 0;
    for (int i = 0; i < KC; i++) {
        if (i + 1 < KC) { CP_WAIT1(); } else { CP_WAIT0(); }
        __syncthreads();
        if (i + 2 < KC) load_stage((st + 2) % 3, (i + 2) << 5);

#pragma unroll
        for (int kb = 0; kb < 2; kb++) {
            uint32_t a[4][4];
#pragma unroll
            for (int mi = 0; mi < 4; mi++)
                ldsm_x4(a[mi], smem_u32(&S.As[st][arow + mi * 16][acol + kb * 16]));
            uint32_t b[4][4];
#pragma unroll
            for (int p = 0; p < 4; p++)
                ldsm_x4(b[p], smem_u32(&S.Bs[st][brow + p * 16][bcol + kb * 16]));
#pragma unroll
            for (int mi = 0; mi < 4; mi++)
#pragma unroll
                for (int ni = 0; ni < 8; ni++)
                    mma_f16(acc[mi][ni], a[mi],
                            b[ni >> 1][2 * (ni & 1)], b[ni >> 1][2 * (ni & 1) + 1]);
        }
        st = (st + 1) % 3;
    }

    // epilogue
#pragma unroll
    for (int mi = 0; mi < 4; mi++) {
        int r0 = bm + wm + mi * 16 + g4;
#pragma unroll
        for (int ni = 0; ni < 8; ni++) {
            int c0 = bn + wn + ni * 8 + 2 * l4;
            if (OUT_HALF) {
                __half* Ch = (__half*)Cv;
                *(__half2*)&Ch[(size_t)r0 * N + c0] =
                    __floats2half2_rn(acc[mi][ni][0], acc[mi][ni][1]);
                *(__half2*)&Ch[(size_t)(r0 + 8) * N + c0] =
                    __floats2half2_rn(acc[mi][ni][2], acc[mi][ni][3]);
            } else {
                float* Cf = (float*)Cv;
                *(float2*)&Cf[(size_t)r0 * N + c0]       = make_float2(acc[mi][ni][0], acc[mi][ni][1]);
                *(float2*)&Cf[(size_t)(r0 + 8) * N + c0] = make_float2(acc[mi][ni][2], acc[mi][ni][3]);
            }
        }
    }
}

// ===========================================================================
// fp16 tensor-core flash attention (unchanged from round 6).
// ===========================================================================
struct AttnSmemH {
    __half Qs[128][72];
    __half Ks[2][64][72];
    __half Vs[2][64][72];
};
#define ATTN_SMEM_BYTES ((int)sizeof(AttnSmemH))

__global__ __launch_bounds__(256, 2)
void attn_h(const __half* __restrict__ qkv, __half* __restrict__ out)
{
    extern __shared__ char sm_raw[];
    AttnSmemH& S = *reinterpret_cast<AttnSmemH*>(sm_raw);

    const int tid  = threadIdx.x;
    const int wid  = tid >> 5;
    const int lane = tid & 31;
    const int g4   = lane >> 2;
    const int l4   = lane & 3;
    const int q0   = blockIdx.x * 128;
    const int h    = blockIdx.y;
    const int b    = blockIdx.z;
    const int qrow = wid * 16;

    const __half* base = qkv + (size_t)b * SEQ * DIM3 + h * HDIM;
    const __half* qg = base;
    const __half* kg = base + DIM;
    const __half* vg = base + 2 * DIM;

    const int frow = (lane & 7) + ((lane >> 3) & 1) * 8;
    const int fcol = (lane >> 4) * 8;
    const int krow = (lane & 7) + (lane >> 4) * 8;
    const int kcol = ((lane >> 3) & 1) * 8;
    const int vrow = (lane & 7) + ((lane >> 3) & 1) * 8;
    const int vcol = (lane >> 4) * 8;

#pragma unroll
    for (int u = 0; u < 4; u++) {
        int ch = tid + u * 256;
        int r  = ch >> 3;
        int j  = ch & 7;
        cp_async16(smem_u32(&S.Qs[r][j * 8]), qg + (size_t)(q0 + r) * DIM3 + j * 8);
    }
    CP_COMMIT();

    auto load_kv = [&](int s, int t0) {
#pragma unroll
        for (int u = 0; u < 2; u++) {
            int ch = tid + u * 256;
            int r  = ch >> 3;
            int j  = ch & 7;
            cp_async16(smem_u32(&S.Ks[s][r][j * 8]), kg + (size_t)(t0 + r) * DIM3 + j * 8);
            cp_async16(smem_u32(&S.Vs[s][r][j * 8]), vg + (size_t)(t0 + r) * DIM3 + j * 8);
        }
        CP_COMMIT();
    };

    load_kv(0, 0);
    CP_WAIT0();
    __syncthreads();

    uint32_t Qf[4][4];
#pragma unroll
    for (int kb = 0; kb < 4; kb++)
        ldsm_x4(Qf[kb], smem_u32(&S.Qs[qrow + frow][fcol + kb * 16]));

    float m2[2] = { -1e30f, -1e30f };
    float l[2]  = { 0.f, 0.f };
    float O[8][4];
#pragma unroll
    for (int ni = 0; ni < 8; ni++)
#pragma unroll
        for (int r = 0; r < 4; r++) O[ni][r] = 0.f;

    const int NT = SEQ / 64;

    for (int it = 0; it < NT; it++) {
        const int s = it & 1;
        if (it + 1 < NT) load_kv(s ^ 1, (it + 1) * 64);

        float sreg[8][4];
#pragma unroll
        for (int ni = 0; ni < 8; ni++)
#pragma unroll
            for (int r = 0; r < 4; r++) sreg[ni][r] = 0.f;

#pragma unroll
        for (int kb = 0; kb < 4; kb++) {
#pragma unroll
            for (int p = 0; p < 4; p++) {
                uint32_t kf[4];
                ldsm_x4(kf, smem_u32(&S.Ks[s][p * 16 + krow][kcol + kb * 16]));
                mma_f16(sreg[2 * p],     Qf[kb], kf[0], kf[1]);
                mma_f16(sreg[2 * p + 1], Qf[kb], kf[2], kf[3]);
            }
        }

        float mx0 = -1e30f, mx1 = -1e30f;
#pragma unroll
        for (int ni = 0; ni < 8; ni++) {
            sreg[ni][0] *= SCALE_LOG2E; sreg[ni][1] *= SCALE_LOG2E;
            sreg[ni][2] *= SCALE_LOG2E; sreg[ni][3] *= SCALE_LOG2E;
            mx0 = fmaxf(mx0, fmaxf(sreg[ni][0], sreg[ni][1]));
            mx1 = fmaxf(mx1, fmaxf(sreg[ni][2], sreg[ni][3]));
        }
        mx0 = fmaxf(mx0, __shfl_xor_sync(0xffffffffu, mx0, 1));
        mx0 = fmaxf(mx0, __shfl_xor_sync(0xffffffffu, mx0, 2));
        mx1 = fmaxf(mx1, __shfl_xor_sync(0xffffffffu, mx1, 1));
        mx1 = fmaxf(mx1, __shfl_xor_sync(0xffffffffu, mx1, 2));

        const float mn0 = fmaxf(m2[0], mx0);
        const float mn1 = fmaxf(m2[1], mx1);
        const float al0 = fast_exp2(m2[0] - mn0);
        const float al1 = fast_exp2(m2[1] - mn1);

        uint32_t Pf[4][4];
        float s0 = 0.f, s1 = 0.f;
#pragma unroll
        for (int ni = 0; ni < 8; ni++) {
            float p0 = fast_exp2(sreg[ni][0] - mn0);
            float p1 = fast_exp2(sreg[ni][1] - mn0);
            float p2 = fast_exp2(sreg[ni][2] - mn1);
            float p3 = fast_exp2(sreg[ni][3] - mn1);
            s0 += p0 + p1;
            s1 += p2 + p3;
            Pf[ni >> 1][2 * (ni & 1)]     = h2_pack(p0, p1);
            Pf[ni >> 1][2 * (ni & 1) + 1] = h2_pack(p2, p3);
        }
        s0 += __shfl_xor_sync(0xffffffffu, s0, 1);
        s0 += __shfl_xor_sync(0xffffffffu, s0, 2);
        s1 += __shfl_xor_sync(0xffffffffu, s1, 1);
        s1 += __shfl_xor_sync(0xffffffffu, s1, 2);

        l[0] = l[0] * al0 + s0;
        l[1] = l[1] * al1 + s1;
        m2[0] = mn0;
        m2[1] = mn1;

#pragma unroll
        for (int ni = 0; ni < 8; ni++) {
            O[ni][0] *= al0; O[ni][1] *= al0;
            O[ni][2] *= al1; O[ni][3] *= al1;
        }

#pragma unroll
        for (int kb = 0; kb < 4; kb++) {
#pragma unroll
            for (int p = 0; p < 4; p++) {
                uint32_t vf[4];
                ldsm_x4_t(vf, smem_u32(&S.Vs[s][kb * 16 + vrow][vcol + p * 16]));
                mma_f16(O[2 * p],     Pf[kb], vf[0], vf[1]);
                mma_f16(O[2 * p + 1], Pf[kb], vf[2], vf[3]);
            }
        }

        if (it + 1 < NT) CP_WAIT0();
        __syncthreads();
    }

    const float inv0 = 1.f / l[0];
    const float inv1 = 1.f / l[1];
    __half* ob = out + (size_t)b * SEQ * DIM + h * HDIM;
    const int r0 = q0 + qrow + g4;
#pragma unroll
    for (int ni = 0; ni < 8; ni++) {
        const int col = ni * 8 + 2 * l4;
        *(__half2*)&ob[(size_t)r0 * DIM + col] =
            __floats2half2_rn(O[ni][0] * inv0, O[ni][1] * inv0);
        *(__half2*)&ob[(size_t)(r0 + 8) * DIM + col] =
            __floats2half2_rn(O[ni][2] * inv1, O[ni][3] * inv1);
    }
}

// ===========================================================================
extern "C" void kernel_launch(void* const* d_in, const int* in_sizes, int n_in,
                              void* d_out, int out_size)
{
    const float* x     = (const float*)d_in[0];
    const float* Wqkv  = (const float*)d_in[1];
    const float* Wproj = (const float*)d_in[2];
    float*       outp  = (float*)d_out;

    __half* qkvh;   cudaGetSymbolAddress((void**)&qkvh,   g_qkvh);
    __half* attnh;  cudaGetSymbolAddress((void**)&attnh,  g_attnh);
    __half* xh;     cudaGetSymbolAddress((void**)&xh,     g_xh);
    __half* wqkvT;  cudaGetSymbolAddress((void**)&wqkvT,  g_wqkvTh);
    __half* wprojT; cudaGetSymbolAddress((void**)&wprojT, g_wprojTh);

    static bool attr_set = false;
    if (!attr_set) {
        cudaFuncSetAttribute(attn_h, cudaFuncAttributeMaxDynamicSharedMemorySize,
                             ATTN_SMEM_BYTES);
        cudaFuncSetAttribute(gemm_h<true>, cudaFuncAttributeMaxDynamicSharedMemorySize,
                             GEMM_SMEM_BYTES);
        cudaFuncSetAttribute(gemm_h<false>, cudaFuncAttributeMaxDynamicSharedMemorySize,
                             GEMM_SMEM_BYTES);
        attr_set = true;
    }

    // 0) operand prep: fp32 -> fp16 (+ weight transposes)
    {
        int n4 = MROWS * DIM / 4;
        f2h_k<<<(n4 + 255) / 256, 256>>>(x, xh, n4);
        transpose_h<<<dim3(DIM3 / 32, DIM / 32), dim3(32, 8)>>>(Wqkv,  wqkvT,  DIM, DIM3);
        transpose_h<<<dim3(DIM  / 32, DIM / 32), dim3(32, 8)>>>(Wproj, wprojT, DIM, DIM);
    }

    // 1) qkv = x @ Wqkv   (half out)
    gemm_h<true><<<dim3(DIM3 / 128, MROWS / 128), 128, GEMM_SMEM_BYTES>>>(xh, wqkvT, qkvh, MROWS, DIM3, DIM);

    // 2) attention (fp16 tensor core, register-resident P)
    attn_h<<<dim3(SEQ / 128, NHEAD, BATCH), 256, ATTN_SMEM_BYTES>>>(qkvh, attnh);

    // 3) out = attn @ Wproj (float out)
    gemm_h<false><<<dim3(DIM / 128, MROWS / 128), 128, GEMM_SMEM_BYTES>>>(attnh, wprojT, outp, MROWS, DIM, DIM);
}

// round 8
// speedup vs baseline: 7.5575x; 1.0225x over previous
#include <cuda_runtime.h>
#include <cuda_fp16.h>
#include <math.h>
#include <stdint.h>

// Problem dims (fixed)
#define BATCH 2
#define SEQ   2048
#define DIM   1024
#define NHEAD 16
#define HDIM  64
#define DIM3  (3*DIM)
#define MROWS (BATCH*SEQ)      // 4096
#define SCALE_LOG2E 0.1803368801111729f   // 64^-0.5 * log2(e)

// Scratch (device globals; allocation-free rule)
__device__ __half g_qkvh  [ (size_t)BATCH * SEQ * DIM3 ];
__device__ __half g_attnh [ (size_t)BATCH * SEQ * DIM  ];
__device__ __half g_xh    [ (size_t)MROWS * DIM ];
__device__ __half g_wqkvTh[ (size_t)DIM3 * DIM ];
__device__ __half g_wprojTh[ (size_t)DIM * DIM ];

// ===========================================================================
// helpers
// ===========================================================================
__device__ __forceinline__ uint32_t smem_u32(const void* p) {
    uint32_t a;
    asm("{ .reg .u64 t; cvta.to.shared.u64 t, %1; cvt.u32.u64 %0, t; }" : "=r"(a) : "l"(p));
    return a;
}
__device__ __forceinline__ float fast_exp2(float x) {
    float y;
    asm("ex2.approx.ftz.f32 %0, %1;" : "=f"(y) : "f"(x));
    return y;
}
// exp2 of two f32 values -> packed half2 (one MUFU op), result ready as mma operand
__device__ __forceinline__ uint32_t exp2_h2(float a, float b) {
    __half2 h = __floats2half2_rn(a, b);
    uint32_t in = *reinterpret_cast<uint32_t*>(&h);
    uint32_t r;
    asm("ex2.approx.f16x2 %0, %1;" : "=r"(r) : "r"(in));
    return r;
}
__device__ __forceinline__ float2 h2_to_f2(uint32_t u) {
    __half2 h = *reinterpret_cast<__half2*>(&u);
    return __half22float2(h);
}
__device__ __forceinline__ void cp_async16(uint32_t saddr, const void* gptr) {
    asm volatile("cp.async.cg.shared.global [%0], [%1], 16;" :: "r"(saddr), "l"(gptr) : "memory");
}
#define CP_COMMIT() asm volatile("cp.async.commit_group;" ::: "memory")
#define CP_WAIT0()  asm volatile("cp.async.wait_group 0;" ::: "memory")
#define CP_WAIT1()  asm volatile("cp.async.wait_group 1;" ::: "memory")

__device__ __forceinline__ void ldsm_x4(uint32_t* r, uint32_t addr) {
    asm volatile("ldmatrix.sync.aligned.m8n8.x4.shared.b16 {%0,%1,%2,%3}, [%4];"
        : "=r"(r[0]), "=r"(r[1]), "=r"(r[2]), "=r"(r[3]) : "r"(addr));
}
__device__ __forceinline__ void ldsm_x4_t(uint32_t* r, uint32_t addr) {
    asm volatile("ldmatrix.sync.aligned.m8n8.x4.trans.shared.b16 {%0,%1,%2,%3}, [%4];"
        : "=r"(r[0]), "=r"(r[1]), "=r"(r[2]), "=r"(r[3]) : "r"(addr));
}

// mma m16n8k16 fp16 inputs, fp32 accum
__device__ __forceinline__ void mma_f16(float* c, const uint32_t* a, uint32_t b0, uint32_t b1) {
    asm volatile(
        "mma.sync.aligned.m16n8k16.row.col.f32.f16.f16.f32 "
        "{%0,%1,%2,%3}, {%4,%5,%6,%7}, {%8,%9}, {%0,%1,%2,%3};"
        : "+f"(c[0]), "+f"(c[1]), "+f"(c[2]), "+f"(c[3])
        : "r"(a[0]), "r"(a[1]), "r"(a[2]), "r"(a[3]), "r"(b0), "r"(b1));
}

// ===========================================================================
// prep kernels
// ===========================================================================
__global__ void f2h_k(const float* __restrict__ in, __half* __restrict__ out, int n4)
{
    int i = blockIdx.x * blockDim.x + threadIdx.x;
    if (i < n4) {
        float4 v = ((const float4*)in)[i];
        ((__half2*)out)[2 * i]     = __floats2half2_rn(v.x, v.y);
        ((__half2*)out)[2 * i + 1] = __floats2half2_rn(v.z, v.w);
    }
}

// out[C][R] = half(in[R][C])
__global__ void transpose_h(const float* __restrict__ in, __half* __restrict__ out, int R, int C)
{
    __shared__ float t[32][33];
    int bx = blockIdx.x * 32, by = blockIdx.y * 32;
    int x = bx + threadIdx.x;
#pragma unroll
    for (int j = 0; j < 32; j += 8) {
        int y = by + threadIdx.y + j;
        t[threadIdx.y + j][threadIdx.x] = in[(size_t)y * C + x];
    }
    __syncthreads();
    int x2 = by + threadIdx.x;
#pragma unroll
    for (int j = 0; j < 32; j += 8) {
        int y2 = bx + threadIdx.y + j;
        out[(size_t)y2 * R + x2] = __float2half_rn(t[threadIdx.x][threadIdx.y + j]);
    }
}

// ===========================================================================
// fp16 mma GEMM (unchanged from round 7): 128x128 CTA tile, BK=32,
// 128 thr (4 warps 2x2, 64x64 warp tiles), 3-stage cp.async pipeline.
// ===========================================================================
struct GSmem {
    __half As[3][128][40];
    __half Bs[3][128][40];
};
#define GEMM_SMEM_BYTES ((int)sizeof(GSmem))

template<bool OUT_HALF>
__global__ __launch_bounds__(128, 2)
void gemm_h(const __half* __restrict__ A, const __half* __restrict__ Bt,
            void* __restrict__ Cv, int M, int N, int K)
{
    extern __shared__ char sm_raw[];
    GSmem& S = *reinterpret_cast<GSmem*>(sm_raw);

    const int tid  = threadIdx.x;
    const int wid  = tid >> 5;
    const int lane = tid & 31;
    const int g4   = lane >> 2;
    const int l4   = lane & 3;
    const int wm   = (wid >> 1) * 64;
    const int wn   = (wid & 1) * 64;
    const int bm   = blockIdx.y * 128;
    const int bn   = blockIdx.x * 128;

    const int arow = wm + (lane & 7) + ((lane >> 3) & 1) * 8;
    const int acol = (lane >> 4) * 8;
    const int brow = wn + (lane & 7) + (lane >> 4) * 8;
    const int bcol = ((lane >> 3) & 1) * 8;

    float acc[4][8][4];
#pragma unroll
    for (int mi = 0; mi < 4; mi++)
#pragma unroll
        for (int ni = 0; ni < 8; ni++)
#pragma unroll
            for (int r = 0; r < 4; r++) acc[mi][ni][r] = 0.f;

    const int KC = K >> 5;

    auto load_stage = [&](int st, int k0) {
#pragma unroll
        for (int u = 0; u < 4; u++) {
            int ch  = tid + u * 128;
            int row = ch >> 2;
            int j   = ch & 3;
            cp_async16(smem_u32(&S.As[st][row][j * 8]), A  + (size_t)(bm + row) * K + k0 + j * 8);
            cp_async16(smem_u32(&S.Bs[st][row][j * 8]), Bt + (size_t)(bn + row) * K + k0 + j * 8);
        }
        CP_COMMIT();
    };

    load_stage(0, 0);
    load_stage(1, 32);

    int st = 0;
    for (int i = 0; i < KC; i++) {
        if (i + 1 < KC) { CP_WAIT1(); } else { CP_WAIT0(); }
        __syncthreads();
        if (i + 2 < KC) load_stage((st + 2) % 3, (i + 2) << 5);

#pragma unroll
        for (int kb = 0; kb < 2; kb++) {
            uint32_t a[4][4];
#pragma unroll
            for (int mi = 0; mi < 4; mi++)
                ldsm_x4(a[mi], smem_u32(&S.As[st][arow + mi * 16][acol + kb * 16]));
            uint32_t b[4][4];
#pragma unroll
            for (int p = 0; p < 4; p++)
                ldsm_x4(b[p], smem_u32(&S.Bs[st][brow + p * 16][bcol + kb * 16]));
#pragma unroll
            for (int mi = 0; mi < 4; mi++)
#pragma unroll
                for (int ni = 0; ni < 8; ni++)
                    mma_f16(acc[mi][ni], a[mi],
                            b[ni >> 1][2 * (ni & 1)], b[ni >> 1][2 * (ni & 1) + 1]);
        }
        st = (st + 1) % 3;
    }

#pragma unroll
    for (int mi = 0; mi < 4; mi++) {
        int r0 = bm + wm + mi * 16 + g4;
#pragma unroll
        for (int ni = 0; ni < 8; ni++) {
            int c0 = bn + wn + ni * 8 + 2 * l4;
            if (OUT_HALF) {
                __half* Ch = (__half*)Cv;
                *(__half2*)&Ch[(size_t)r0 * N + c0] =
                    __floats2half2_rn(acc[mi][ni][0], acc[mi][ni][1]);
                *(__half2*)&Ch[(size_t)(r0 + 8) * N + c0] =
                    __floats2half2_rn(acc[mi][ni][2], acc[mi][ni][3]);
            } else {
                float* Cf = (float*)Cv;
                *(float2*)&Cf[(size_t)r0 * N + c0]       = make_float2(acc[mi][ni][0], acc[mi][ni][1]);
                *(float2*)&Cf[(size_t)(r0 + 8) * N + c0] = make_float2(acc[mi][ni][2], acc[mi][ni][3]);
            }
        }
    }
}

// ===========================================================================
// fp16 tensor-core flash attention, 2-strip warps.
// 128 thr / 4 warps; warp owns 32 q-rows (two 16-row strips). K/V fragments
// loaded once per (kb,p), reused by both strips: 0.25 LDSM/MMA.
// exp2 computed in f16x2 (half the MUFU ops; result IS the Pf operand).
// ===========================================================================
struct AttnSmemH {
    __half Qs[128][72];
    __half Ks[2][64][72];
    __half Vs[2][64][72];
};
#define ATTN_SMEM_BYTES ((int)sizeof(AttnSmemH))

__global__ __launch_bounds__(128, 2)
void attn_h(const __half* __restrict__ qkv, __half* __restrict__ out)
{
    extern __shared__ char sm_raw[];
    AttnSmemH& S = *reinterpret_cast<AttnSmemH*>(sm_raw);

    const int tid  = threadIdx.x;
    const int wid  = tid >> 5;
    const int lane = tid & 31;
    const int g4   = lane >> 2;
    const int l4   = lane & 3;
    const int q0   = blockIdx.x * 128;
    const int h    = blockIdx.y;
    const int b    = blockIdx.z;
    const int qrow = wid * 32;          // warp owns rows [qrow, qrow+32)

    const __half* base = qkv + (size_t)b * SEQ * DIM3 + h * HDIM;
    const __half* qg = base;
    const __half* kg = base + DIM;
    const __half* vg = base + 2 * DIM;

    const int frow = (lane & 7) + ((lane >> 3) & 1) * 8;   // A-frag row offset
    const int fcol = (lane >> 4) * 8;                      // A-frag col offset
    const int krow = (lane & 7) + (lane >> 4) * 8;         // K B-frag row
    const int kcol = ((lane >> 3) & 1) * 8;                // K B-frag col
    const int vrow = (lane & 7) + ((lane >> 3) & 1) * 8;   // V B-frag (.trans) row
    const int vcol = (lane >> 4) * 8;                      // V B-frag col

    // ---- Q tile load (128 x 64 halves), 128 threads ----
#pragma unroll
    for (int u = 0; u < 8; u++) {
        int ch = tid + u * 128;          // 0..1023
        int r  = ch >> 3;                // 0..127
        int j  = ch & 7;
        cp_async16(smem_u32(&S.Qs[r][j * 8]), qg + (size_t)(q0 + r) * DIM3 + j * 8);
    }
    CP_COMMIT();

    auto load_kv = [&](int s, int t0) {
#pragma unroll
        for (int u = 0; u < 4; u++) {
            int ch = tid + u * 128;      // 0..511
            int r  = ch >> 3;            // 0..63
            int j  = ch & 7;
            cp_async16(smem_u32(&S.Ks[s][r][j * 8]), kg + (size_t)(t0 + r) * DIM3 + j * 8);
            cp_async16(smem_u32(&S.Vs[s][r][j * 8]), vg + (size_t)(t0 + r) * DIM3 + j * 8);
        }
        CP_COMMIT();
    };

    load_kv(0, 0);
    CP_WAIT0();
    __syncthreads();

    // ---- hoist Q fragments for both strips ----
    uint32_t Qf[2][4][4];
#pragma unroll
    for (int stp = 0; stp < 2; stp++)
#pragma unroll
        for (int kb = 0; kb < 4; kb++)
            ldsm_x4(Qf[stp][kb], smem_u32(&S.Qs[qrow + stp * 16 + frow][fcol + kb * 16]));

    float m2[2][2], l[2][2];
    float O[2][8][4];
#pragma unroll
    for (int stp = 0; stp < 2; stp++) {
        m2[stp][0] = m2[stp][1] = -1e30f;
        l[stp][0]  = l[stp][1]  = 0.f;
#pragma unroll
        for (int ni = 0; ni < 8; ni++)
#pragma unroll
            for (int r = 0; r < 4; r++) O[stp][ni][r] = 0.f;
    }

    const int NT = SEQ / 64;

    for (int it = 0; it < NT; it++) {
        const int s = it & 1;
        if (it + 1 < NT) load_kv(s ^ 1, (it + 1) * 64);

        // ---- QK^T : 32 q-rows x 64 keys; kf shared by both strips ----
        float sreg[2][8][4];
#pragma unroll
        for (int stp = 0; stp < 2; stp++)
#pragma unroll
            for (int ni = 0; ni < 8; ni++)
#pragma unroll
                for (int r = 0; r < 4; r++) sreg[stp][ni][r] = 0.f;

#pragma unroll
        for (int kb = 0; kb < 4; kb++) {
#pragma unroll
            for (int p = 0; p < 4; p++) {
                uint32_t kf[4];
                ldsm_x4(kf, smem_u32(&S.Ks[s][p * 16 + krow][kcol + kb * 16]));
                mma_f16(sreg[0][2 * p],     Qf[0][kb], kf[0], kf[1]);
                mma_f16(sreg[0][2 * p + 1], Qf[0][kb], kf[2], kf[3]);
                mma_f16(sreg[1][2 * p],     Qf[1][kb], kf[0], kf[1]);
                mma_f16(sreg[1][2 * p + 1], Qf[1][kb], kf[2], kf[3]);
            }
        }

        // ---- online softmax per strip (base-2, f16x2 exp) ----
        uint32_t Pf[2][4][4];
#pragma unroll
        for (int stp = 0; stp < 2; stp++) {
            float mx0 = -1e30f, mx1 = -1e30f;
#pragma unroll
            for (int ni = 0; ni < 8; ni++) {
                sreg[stp][ni][0] *= SCALE_LOG2E; sreg[stp][ni][1] *= SCALE_LOG2E;
                sreg[stp][ni][2] *= SCALE_LOG2E; sreg[stp][ni][3] *= SCALE_LOG2E;
                mx0 = fmaxf(mx0, fmaxf(sreg[stp][ni][0], sreg[stp][ni][1]));
                mx1 = fmaxf(mx1, fmaxf(sreg[stp][ni][2], sreg[stp][ni][3]));
            }
            mx0 = fmaxf(mx0, __shfl_xor_sync(0xffffffffu, mx0, 1));
            mx0 = fmaxf(mx0, __shfl_xor_sync(0xffffffffu, mx0, 2));
            mx1 = fmaxf(mx1, __shfl_xor_sync(0xffffffffu, mx1, 1));
            mx1 = fmaxf(mx1, __shfl_xor_sync(0xffffffffu, mx1, 2));

            const float mn0 = fmaxf(m2[stp][0], mx0);
            const float mn1 = fmaxf(m2[stp][1], mx1);
            const float al0 = fast_exp2(m2[stp][0] - mn0);
            const float al1 = fast_exp2(m2[stp][1] - mn1);

            float s0 = 0.f, s1 = 0.f;
#pragma unroll
            for (int ni = 0; ni < 8; ni++) {
                uint32_t e01 = exp2_h2(sreg[stp][ni][0] - mn0, sreg[stp][ni][1] - mn0);
                uint32_t e23 = exp2_h2(sreg[stp][ni][2] - mn1, sreg[stp][ni][3] - mn1);
                Pf[stp][ni >> 1][2 * (ni & 1)]     = e01;
                Pf[stp][ni >> 1][2 * (ni & 1) + 1] = e23;
                float2 f01 = h2_to_f2(e01);
                float2 f23 = h2_to_f2(e23);
                s0 += f01.x + f01.y;
                s1 += f23.x + f23.y;
            }
            s0 += __shfl_xor_sync(0xffffffffu, s0, 1);
            s0 += __shfl_xor_sync(0xffffffffu, s0, 2);
            s1 += __shfl_xor_sync(0xffffffffu, s1, 1);
            s1 += __shfl_xor_sync(0xffffffffu, s1, 2);

            l[stp][0] = l[stp][0] * al0 + s0;
            l[stp][1] = l[stp][1] * al1 + s1;
            m2[stp][0] = mn0;
            m2[stp][1] = mn1;

#pragma unroll
            for (int ni = 0; ni < 8; ni++) {
                O[stp][ni][0] *= al0; O[stp][ni][1] *= al0;
                O[stp][ni][2] *= al1; O[stp][ni][3] *= al1;
            }
        }

        // ---- P @ V ; vf shared by both strips ----
#pragma unroll
        for (int kb = 0; kb < 4; kb++) {
#pragma unroll
            for (int p = 0; p < 4; p++) {
                uint32_t vf[4];
                ldsm_x4_t(vf, smem_u32(&S.Vs[s][kb * 16 + vrow][vcol + p * 16]));
                mma_f16(O[0][2 * p],     Pf[0][kb], vf[0], vf[1]);
                mma_f16(O[0][2 * p + 1], Pf[0][kb], vf[2], vf[3]);
                mma_f16(O[1][2 * p],     Pf[1][kb], vf[0], vf[1]);
                mma_f16(O[1][2 * p + 1], Pf[1][kb], vf[2], vf[3]);
            }
        }

        if (it + 1 < NT) CP_WAIT0();
        __syncthreads();
    }

    // ---- normalize + store (half, feeds GEMM2) ----
    __half* ob = out + (size_t)b * SEQ * DIM + h * HDIM;
#pragma unroll
    for (int stp = 0; stp < 2; stp++) {
        const float inv0 = 1.f / l[stp][0];
        const float inv1 = 1.f / l[stp][1];
        const int r0 = q0 + qrow + stp * 16 + g4;
#pragma unroll
        for (int ni = 0; ni < 8; ni++) {
            const int col = ni * 8 + 2 * l4;
            *(__half2*)&ob[(size_t)r0 * DIM + col] =
                __floats2half2_rn(O[stp][ni][0] * inv0, O[stp][ni][1] * inv0);
            *(__half2*)&ob[(size_t)(r0 + 8) * DIM + col] =
                __floats2half2_rn(O[stp][ni][2] * inv1, O[stp][ni][3] * inv1);
        }
    }
}

// ===========================================================================
extern "C" void kernel_launch(void* const* d_in, const int* in_sizes, int n_in,
                              void* d_out, int out_size)
{
    const float* x     = (const float*)d_in[0];
    const float* Wqkv  = (const float*)d_in[1];
    const float* Wproj = (const float*)d_in[2];
    float*       outp  = (float*)d_out;

    __half* qkvh;   cudaGetSymbolAddress((void**)&qkvh,   g_qkvh);
    __half* attnh;  cudaGetSymbolAddress((void**)&attnh,  g_attnh);
    __half* xh;     cudaGetSymbolAddress((void**)&xh,     g_xh);
    __half* wqkvT;  cudaGetSymbolAddress((void**)&wqkvT,  g_wqkvTh);
    __half* wprojT; cudaGetSymbolAddress((void**)&wprojT, g_wprojTh);

    static bool attr_set = false;
    if (!attr_set) {
        cudaFuncSetAttribute(attn_h, cudaFuncAttributeMaxDynamicSharedMemorySize,
                             ATTN_SMEM_BYTES);
        cudaFuncSetAttribute(gemm_h<true>, cudaFuncAttributeMaxDynamicSharedMemorySize,
                             GEMM_SMEM_BYTES);
        cudaFuncSetAttribute(gemm_h<false>, cudaFuncAttributeMaxDynamicSharedMemorySize,
                             GEMM_SMEM_BYTES);
        attr_set = true;
    }

    // 0) operand prep: fp32 -> fp16 (+ weight transposes)
    {
        int n4 = MROWS * DIM / 4;
        f2h_k<<<(n4 + 255) / 256, 256>>>(x, xh, n4);
        transpose_h<<<dim3(DIM3 / 32, DIM / 32), dim3(32, 8)>>>(Wqkv,  wqkvT,  DIM, DIM3);
        transpose_h<<<dim3(DIM  / 32, DIM / 32), dim3(32, 8)>>>(Wproj, wprojT, DIM, DIM);
    }

    // 1) qkv = x @ Wqkv   (half out)
    gemm_h<true><<<dim3(DIM3 / 128, MROWS / 128), 128, GEMM_SMEM_BYTES>>>(xh, wqkvT, qkvh, MROWS, DIM3, DIM);

    // 2) attention (fp16 tensor core, 2-strip warps, register-resident P)
    attn_h<<<dim3(SEQ / 128, NHEAD, BATCH), 128, ATTN_SMEM_BYTES>>>(qkvh, attnh);

    // 3) out = attn @ Wproj (float out)
    gemm_h<false><<<dim3(DIM / 128, MROWS / 128), 128, GEMM_SMEM_BYTES>>>(attnh, wprojT, outp, MROWS, DIM, DIM);
}

// round 9
// speedup vs baseline: 7.7372x; 1.0238x over previous
#include <cuda_runtime.h>
#include <cuda_fp16.h>
#include <math.h>
#include <stdint.h>

// Problem dims (fixed)
#define BATCH 2
#define SEQ   2048
#define DIM   1024
#define NHEAD 16
#define HDIM  64
#define DIM3  (3*DIM)
#define MROWS (BATCH*SEQ)      // 4096
#define SCALE_LOG2E 0.1803368801111729f   // 64^-0.5 * log2(e)

// Scratch (device globals; allocation-free rule)
__device__ __half g_qkvh  [ (size_t)BATCH * SEQ * DIM3 ];
__device__ __half g_attnh [ (size_t)BATCH * SEQ * DIM  ];
__device__ __half g_xh    [ (size_t)MROWS * DIM ];
__device__ __half g_wqkvTh[ (size_t)DIM3 * DIM ];
__device__ __half g_wprojTh[ (size_t)DIM * DIM ];

// ===========================================================================
// helpers
// ===========================================================================
__device__ __forceinline__ uint32_t smem_u32(const void* p) {
    uint32_t a;
    asm("{ .reg .u64 t; cvta.to.shared.u64 t, %1; cvt.u32.u64 %0, t; }" : "=r"(a) : "l"(p));
    return a;
}
__device__ __forceinline__ float fast_exp2(float x) {
    float y;
    asm("ex2.approx.ftz.f32 %0, %1;" : "=f"(y) : "f"(x));
    return y;
}
// exp2 of two f32 values -> packed half2 (one MUFU op), result ready as mma operand
__device__ __forceinline__ uint32_t exp2_h2(float a, float b) {
    __half2 h = __floats2half2_rn(a, b);
    uint32_t in = *reinterpret_cast<uint32_t*>(&h);
    uint32_t r;
    asm("ex2.approx.f16x2 %0, %1;" : "=r"(r) : "r"(in));
    return r;
}
__device__ __forceinline__ float2 h2_to_f2(uint32_t u) {
    __half2 h = *reinterpret_cast<__half2*>(&u);
    return __half22float2(h);
}
__device__ __forceinline__ void cp_async16(uint32_t saddr, const void* gptr) {
    asm volatile("cp.async.cg.shared.global [%0], [%1], 16;" :: "r"(saddr), "l"(gptr) : "memory");
}
#define CP_COMMIT() asm volatile("cp.async.commit_group;" ::: "memory")
#define CP_WAIT0()  asm volatile("cp.async.wait_group 0;" ::: "memory")
#define CP_WAIT1()  asm volatile("cp.async.wait_group 1;" ::: "memory")

__device__ __forceinline__ void ldsm_x4(uint32_t* r, uint32_t addr) {
    asm volatile("ldmatrix.sync.aligned.m8n8.x4.shared.b16 {%0,%1,%2,%3}, [%4];"
        : "=r"(r[0]), "=r"(r[1]), "=r"(r[2]), "=r"(r[3]) : "r"(addr));
}
__device__ __forceinline__ void ldsm_x4_t(uint32_t* r, uint32_t addr) {
    asm volatile("ldmatrix.sync.aligned.m8n8.x4.trans.shared.b16 {%0,%1,%2,%3}, [%4];"
        : "=r"(r[0]), "=r"(r[1]), "=r"(r[2]), "=r"(r[3]) : "r"(addr));
}

// mma m16n8k16 fp16 inputs, fp32 accum
__device__ __forceinline__ void mma_f16(float* c, const uint32_t* a, uint32_t b0, uint32_t b1) {
    asm volatile(
        "mma.sync.aligned.m16n8k16.row.col.f32.f16.f16.f32 "
        "{%0,%1,%2,%3}, {%4,%5,%6,%7}, {%8,%9}, {%0,%1,%2,%3};"
        : "+f"(c[0]), "+f"(c[1]), "+f"(c[2]), "+f"(c[3])
        : "r"(a[0]), "r"(a[1]), "r"(a[2]), "r"(a[3]), "r"(b0), "r"(b1));
}

// ===========================================================================
// prep kernels
// ===========================================================================
__global__ void f2h_k(const float* __restrict__ in, __half* __restrict__ out, int n4)
{
    int i = blockIdx.x * blockDim.x + threadIdx.x;
    if (i < n4) {
        float4 v = ((const float4*)in)[i];
        ((__half2*)out)[2 * i]     = __floats2half2_rn(v.x, v.y);
        ((__half2*)out)[2 * i + 1] = __floats2half2_rn(v.z, v.w);
    }
}

// out[C][R] = half(in[R][C])
__global__ void transpose_h(const float* __restrict__ in, __half* __restrict__ out, int R, int C)
{
    __shared__ float t[32][33];
    int bx = blockIdx.x * 32, by = blockIdx.y * 32;
    int x = bx + threadIdx.x;
#pragma unroll
    for (int j = 0; j < 32; j += 8) {
        int y = by + threadIdx.y + j;
        t[threadIdx.y + j][threadIdx.x] = in[(size_t)y * C + x];
    }
    __syncthreads();
    int x2 = by + threadIdx.x;
#pragma unroll
    for (int j = 0; j < 32; j += 8) {
        int y2 = bx + threadIdx.y + j;
        out[(size_t)y2 * R + x2] = __float2half_rn(t[threadIdx.x][threadIdx.y + j]);
    }
}

// ===========================================================================
// fp16 mma GEMM: 128x128 CTA tile, BK=64, 2-stage double buffer
// (same 64-col prefetch distance as 3x32, HALF the barriers).
// 128 thr (4 warps 2x2, 64x64 warp tiles). Per chunk: 32 LDSM : 128 MMA.
// ===========================================================================
struct GSmem {
    __half As[2][128][72];
    __half Bs[2][128][72];
};
#define GEMM_SMEM_BYTES ((int)sizeof(GSmem))

template<bool OUT_HALF>
__global__ __launch_bounds__(128, 2)
void gemm_h(const __half* __restrict__ A, const __half* __restrict__ Bt,
            void* __restrict__ Cv, int M, int N, int K)
{
    extern __shared__ char sm_raw[];
    GSmem& S = *reinterpret_cast<GSmem*>(sm_raw);

    const int tid  = threadIdx.x;
    const int wid  = tid >> 5;
    const int lane = tid & 31;
    const int g4   = lane >> 2;
    const int l4   = lane & 3;
    const int wm   = (wid >> 1) * 64;
    const int wn   = (wid & 1) * 64;
    const int bm   = blockIdx.y * 128;
    const int bn   = blockIdx.x * 128;

    const int arow = wm + (lane & 7) + ((lane >> 3) & 1) * 8;   // + mi*16
    const int acol = (lane >> 4) * 8;                           // + kb*16
    const int brow = wn + (lane & 7) + (lane >> 4) * 8;         // + p*16
    const int bcol = ((lane >> 3) & 1) * 8;                     // + kb*16

    float acc[4][8][4];
#pragma unroll
    for (int mi = 0; mi < 4; mi++)
#pragma unroll
        for (int ni = 0; ni < 8; ni++)
#pragma unroll
            for (int r = 0; r < 4; r++) acc[mi][ni][r] = 0.f;

    const int KC = K >> 6;   // BK=64 chunks

    auto load_stage = [&](int st, int k0) {
#pragma unroll
        for (int u = 0; u < 8; u++) {
            int ch  = tid + u * 128;        // 0..1023
            int row = ch >> 3;              // 0..127
            int j   = ch & 7;               // 8 chunks of 8 halves = 64 cols
            cp_async16(smem_u32(&S.As[st][row][j * 8]), A  + (size_t)(bm + row) * K + k0 + j * 8);
            cp_async16(smem_u32(&S.Bs[st][row][j * 8]), Bt + (size_t)(bn + row) * K + k0 + j * 8);
        }
        CP_COMMIT();
    };

    load_stage(0, 0);

    for (int i = 0; i < KC; i++) {
        const int st = i & 1;
        if (i + 1 < KC) {
            load_stage(st ^ 1, (i + 1) << 6);
            CP_WAIT1();
        } else {
            CP_WAIT0();
        }
        __syncthreads();

#pragma unroll
        for (int kb = 0; kb < 4; kb++) {
            uint32_t a[4][4];
#pragma unroll
            for (int mi = 0; mi < 4; mi++)
                ldsm_x4(a[mi], smem_u32(&S.As[st][arow + mi * 16][acol + kb * 16]));
            uint32_t b[4][4];
#pragma unroll
            for (int p = 0; p < 4; p++)
                ldsm_x4(b[p], smem_u32(&S.Bs[st][brow + p * 16][bcol + kb * 16]));
#pragma unroll
            for (int mi = 0; mi < 4; mi++)
#pragma unroll
                for (int ni = 0; ni < 8; ni++)
                    mma_f16(acc[mi][ni], a[mi],
                            b[ni >> 1][2 * (ni & 1)], b[ni >> 1][2 * (ni & 1) + 1]);
        }
        __syncthreads();
    }

    // epilogue
#pragma unroll
    for (int mi = 0; mi < 4; mi++) {
        int r0 = bm + wm + mi * 16 + g4;
#pragma unroll
        for (int ni = 0; ni < 8; ni++) {
            int c0 = bn + wn + ni * 8 + 2 * l4;
            if (OUT_HALF) {
                __half* Ch = (__half*)Cv;
                *(__half2*)&Ch[(size_t)r0 * N + c0] =
                    __floats2half2_rn(acc[mi][ni][0], acc[mi][ni][1]);
                *(__half2*)&Ch[(size_t)(r0 + 8) * N + c0] =
                    __floats2half2_rn(acc[mi][ni][2], acc[mi][ni][3]);
            } else {
                float* Cf = (float*)Cv;
                *(float2*)&Cf[(size_t)r0 * N + c0]       = make_float2(acc[mi][ni][0], acc[mi][ni][1]);
                *(float2*)&Cf[(size_t)(r0 + 8) * N + c0] = make_float2(acc[mi][ni][2], acc[mi][ni][3]);
            }
        }
    }
}

// ===========================================================================
// fp16 tensor-core flash attention, 2-strip warps (unchanged from round 8).
// ===========================================================================
struct AttnSmemH {
    __half Qs[128][72];
    __half Ks[2][64][72];
    __half Vs[2][64][72];
};
#define ATTN_SMEM_BYTES ((int)sizeof(AttnSmemH))

__global__ __launch_bounds__(128, 2)
void attn_h(const __half* __restrict__ qkv, __half* __restrict__ out)
{
    extern __shared__ char sm_raw[];
    AttnSmemH& S = *reinterpret_cast<AttnSmemH*>(sm_raw);

    const int tid  = threadIdx.x;
    const int wid  = tid >> 5;
    const int lane = tid & 31;
    const int g4   = lane >> 2;
    const int l4   = lane & 3;
    const int q0   = blockIdx.x * 128;
    const int h    = blockIdx.y;
    const int b    = blockIdx.z;
    const int qrow = wid * 32;

    const __half* base = qkv + (size_t)b * SEQ * DIM3 + h * HDIM;
    const __half* qg = base;
    const __half* kg = base + DIM;
    const __half* vg = base + 2 * DIM;

    const int frow = (lane & 7) + ((lane >> 3) & 1) * 8;
    const int fcol = (lane >> 4) * 8;
    const int krow = (lane & 7) + (lane >> 4) * 8;
    const int kcol = ((lane >> 3) & 1) * 8;
    const int vrow = (lane & 7) + ((lane >> 3) & 1) * 8;
    const int vcol = (lane >> 4) * 8;

#pragma unroll
    for (int u = 0; u < 8; u++) {
        int ch = tid + u * 128;
        int r  = ch >> 3;
        int j  = ch & 7;
        cp_async16(smem_u32(&S.Qs[r][j * 8]), qg + (size_t)(q0 + r) * DIM3 + j * 8);
    }
    CP_COMMIT();

    auto load_kv = [&](int s, int t0) {
#pragma unroll
        for (int u = 0; u < 4; u++) {
            int ch = tid + u * 128;
            int r  = ch >> 3;
            int j  = ch & 7;
            cp_async16(smem_u32(&S.Ks[s][r][j * 8]), kg + (size_t)(t0 + r) * DIM3 + j * 8);
            cp_async16(smem_u32(&S.Vs[s][r][j * 8]), vg + (size_t)(t0 + r) * DIM3 + j * 8);
        }
        CP_COMMIT();
    };

    load_kv(0, 0);
    CP_WAIT0();
    __syncthreads();

    uint32_t Qf[2][4][4];
#pragma unroll
    for (int stp = 0; stp < 2; stp++)
#pragma unroll
        for (int kb = 0; kb < 4; kb++)
            ldsm_x4(Qf[stp][kb], smem_u32(&S.Qs[qrow + stp * 16 + frow][fcol + kb * 16]));

    float m2[2][2], l[2][2];
    float O[2][8][4];
#pragma unroll
    for (int stp = 0; stp < 2; stp++) {
        m2[stp][0] = m2[stp][1] = -1e30f;
        l[stp][0]  = l[stp][1]  = 0.f;
#pragma unroll
        for (int ni = 0; ni < 8; ni++)
#pragma unroll
            for (int r = 0; r < 4; r++) O[stp][ni][r] = 0.f;
    }

    const int NT = SEQ / 64;

    for (int it = 0; it < NT; it++) {
        const int s = it & 1;
        if (it + 1 < NT) load_kv(s ^ 1, (it + 1) * 64);

        float sreg[2][8][4];
#pragma unroll
        for (int stp = 0; stp < 2; stp++)
#pragma unroll
            for (int ni = 0; ni < 8; ni++)
#pragma unroll
                for (int r = 0; r < 4; r++) sreg[stp][ni][r] = 0.f;

#pragma unroll
        for (int kb = 0; kb < 4; kb++) {
#pragma unroll
            for (int p = 0; p < 4; p++) {
                uint32_t kf[4];
                ldsm_x4(kf, smem_u32(&S.Ks[s][p * 16 + krow][kcol + kb * 16]));
                mma_f16(sreg[0][2 * p],     Qf[0][kb], kf[0], kf[1]);
                mma_f16(sreg[0][2 * p + 1], Qf[0][kb], kf[2], kf[3]);
                mma_f16(sreg[1][2 * p],     Qf[1][kb], kf[0], kf[1]);
                mma_f16(sreg[1][2 * p + 1], Qf[1][kb], kf[2], kf[3]);
            }
        }

        uint32_t Pf[2][4][4];
#pragma unroll
        for (int stp = 0; stp < 2; stp++) {
            float mx0 = -1e30f, mx1 = -1e30f;
#pragma unroll
            for (int ni = 0; ni < 8; ni++) {
                sreg[stp][ni][0] *= SCALE_LOG2E; sreg[stp][ni][1] *= SCALE_LOG2E;
                sreg[stp][ni][2] *= SCALE_LOG2E; sreg[stp][ni][3] *= SCALE_LOG2E;
                mx0 = fmaxf(mx0, fmaxf(sreg[stp][ni][0], sreg[stp][ni][1]));
                mx1 = fmaxf(mx1, fmaxf(sreg[stp][ni][2], sreg[stp][ni][3]));
            }
            mx0 = fmaxf(mx0, __shfl_xor_sync(0xffffffffu, mx0, 1));
            mx0 = fmaxf(mx0, __shfl_xor_sync(0xffffffffu, mx0, 2));
            mx1 = fmaxf(mx1, __shfl_xor_sync(0xffffffffu, mx1, 1));
            mx1 = fmaxf(mx1, __shfl_xor_sync(0xffffffffu, mx1, 2));

            const float mn0 = fmaxf(m2[stp][0], mx0);
            const float mn1 = fmaxf(m2[stp][1], mx1);
            const float al0 = fast_exp2(m2[stp][0] - mn0);
            const float al1 = fast_exp2(m2[stp][1] - mn1);

            float s0 = 0.f, s1 = 0.f;
#pragma unroll
            for (int ni = 0; ni < 8; ni++) {
                uint32_t e01 = exp2_h2(sreg[stp][ni][0] - mn0, sreg[stp][ni][1] - mn0);
                uint32_t e23 = exp2_h2(sreg[stp][ni][2] - mn1, sreg[stp][ni][3] - mn1);
                Pf[stp][ni >> 1][2 * (ni & 1)]     = e01;
                Pf[stp][ni >> 1][2 * (ni & 1) + 1] = e23;
                float2 f01 = h2_to_f2(e01);
                float2 f23 = h2_to_f2(e23);
                s0 += f01.x + f01.y;
                s1 += f23.x + f23.y;
            }
            s0 += __shfl_xor_sync(0xffffffffu, s0, 1);
            s0 += __shfl_xor_sync(0xffffffffu, s0, 2);
            s1 += __shfl_xor_sync(0xffffffffu, s1, 1);
            s1 += __shfl_xor_sync(0xffffffffu, s1, 2);

            l[stp][0] = l[stp][0] * al0 + s0;
            l[stp][1] = l[stp][1] * al1 + s1;
            m2[stp][0] = mn0;
            m2[stp][1] = mn1;

#pragma unroll
            for (int ni = 0; ni < 8; ni++) {
                O[stp][ni][0] *= al0; O[stp][ni][1] *= al0;
                O[stp][ni][2] *= al1; O[stp][ni][3] *= al1;
            }
        }

#pragma unroll
        for (int kb = 0; kb < 4; kb++) {
#pragma unroll
            for (int p = 0; p < 4; p++) {
                uint32_t vf[4];
                ldsm_x4_t(vf, smem_u32(&S.Vs[s][kb * 16 + vrow][vcol + p * 16]));
                mma_f16(O[0][2 * p],     Pf[0][kb], vf[0], vf[1]);
                mma_f16(O[0][2 * p + 1], Pf[0][kb], vf[2], vf[3]);
                mma_f16(O[1][2 * p],     Pf[1][kb], vf[0], vf[1]);
                mma_f16(O[1][2 * p + 1], Pf[1][kb], vf[2], vf[3]);
            }
        }

        if (it + 1 < NT) CP_WAIT0();
        __syncthreads();
    }

    __half* ob = out + (size_t)b * SEQ * DIM + h * HDIM;
#pragma unroll
    for (int stp = 0; stp < 2; stp++) {
        const float inv0 = 1.f / l[stp][0];
        const float inv1 = 1.f / l[stp][1];
        const int r0 = q0 + qrow + stp * 16 + g4;
#pragma unroll
        for (int ni = 0; ni < 8; ni++) {
            const int col = ni * 8 + 2 * l4;
            *(__half2*)&ob[(size_t)r0 * DIM + col] =
                __floats2half2_rn(O[stp][ni][0] * inv0, O[stp][ni][1] * inv0);
            *(__half2*)&ob[(size_t)(r0 + 8) * DIM + col] =
                __floats2half2_rn(O[stp][ni][2] * inv1, O[stp][ni][3] * inv1);
        }
    }
}

// ===========================================================================
extern "C" void kernel_launch(void* const* d_in, const int* in_sizes, int n_in,
                              void* d_out, int out_size)
{
    const float* x     = (const float*)d_in[0];
    const float* Wqkv  = (const float*)d_in[1];
    const float* Wproj = (const float*)d_in[2];
    float*       outp  = (float*)d_out;

    __half* qkvh;   cudaGetSymbolAddress((void**)&qkvh,   g_qkvh);
    __half* attnh;  cudaGetSymbolAddress((void**)&attnh,  g_attnh);
    __half* xh;     cudaGetSymbolAddress((void**)&xh,     g_xh);
    __half* wqkvT;  cudaGetSymbolAddress((void**)&wqkvT,  g_wqkvTh);
    __half* wprojT; cudaGetSymbolAddress((void**)&wprojT, g_wprojTh);

    static bool attr_set = false;
    if (!attr_set) {
        cudaFuncSetAttribute(attn_h, cudaFuncAttributeMaxDynamicSharedMemorySize,
                             ATTN_SMEM_BYTES);
        cudaFuncSetAttribute(gemm_h<true>, cudaFuncAttributeMaxDynamicSharedMemorySize,
                             GEMM_SMEM_BYTES);
        cudaFuncSetAttribute(gemm_h<false>, cudaFuncAttributeMaxDynamicSharedMemorySize,
                             GEMM_SMEM_BYTES);
        attr_set = true;
    }

    // 0) operand prep: fp32 -> fp16 (+ weight transposes)
    {
        int n4 = MROWS * DIM / 4;
        f2h_k<<<(n4 + 255) / 256, 256>>>(x, xh, n4);
        transpose_h<<<dim3(DIM3 / 32, DIM / 32), dim3(32, 8)>>>(Wqkv,  wqkvT,  DIM, DIM3);
        transpose_h<<<dim3(DIM  / 32, DIM / 32), dim3(32, 8)>>>(Wproj, wprojT, DIM, DIM);
    }

    // 1) qkv = x @ Wqkv   (half out)
    gemm_h<true><<<dim3(DIM3 / 128, MROWS / 128), 128, GEMM_SMEM_BYTES>>>(xh, wqkvT, qkvh, MROWS, DIM3, DIM);

    // 2) attention (fp16 tensor core, 2-strip warps, register-resident P)
    attn_h<<<dim3(SEQ / 128, NHEAD, BATCH), 128, ATTN_SMEM_BYTES>>>(qkvh, attnh);

    // 3) out = attn @ Wproj (float out)
    gemm_h<false><<<dim3(DIM / 128, MROWS / 128), 128, GEMM_SMEM_BYTES>>>(attnh, wprojT, outp, MROWS, DIM, DIM);
}